// round 15
// baseline (speedup 1.0000x reference)
#include <cuda_runtime.h>
#include <cuda_bf16.h>
#include <math.h>
#include <stdint.h>

// ---------------------------------------------------------------------------
// Problem constants
// ---------------------------------------------------------------------------
#define N_NODES 20000
#define N_EDGES 320000
#define HIDDEN  128
#define HEADS   8
#define LAYERS  3
#define NV      (N_NODES + 1)
#define E_EXP   (NV * 4)                 // 80004 per layer
#define QKV6    (6 * HIDDEN)             // 768: lq|lk|lv|eq|ek|ev

typedef __nv_bfloat16  bf16;
typedef __nv_bfloat162 bf162;

// ---------------------------------------------------------------------------
// Scratch (device globals; no allocations)
// ---------------------------------------------------------------------------
__device__ float g_xv   [(size_t)NV * HIDDEN];
__device__ float g_qkv  [(size_t)NV * QKV6];
__device__ bf16  g_kbuf [(size_t)NV * 256];           // bf16 keys: [local k | exp k]
__device__ float g_agg  [(size_t)NV * 256];           // [local 128 | exp 128]
__device__ float g_h1   [(size_t)NV * 4 * HIDDEN];
// packed + PRE-SPLIT weights (B operands only)
__device__ bf16  g_wqkvh[(size_t)LAYERS * HIDDEN * QKV6];
__device__ bf16  g_wqkvl[(size_t)LAYERS * HIDDEN * QKV6];
__device__ bf16  g_woh  [(size_t)LAYERS * 256 * HIDDEN];
__device__ bf16  g_wol  [(size_t)LAYERS * 256 * HIDDEN];
__device__ bf16  g_w1h  [(size_t)LAYERS * HIDDEN * 512];
__device__ bf16  g_w1l  [(size_t)LAYERS * HIDDEN * 512];
__device__ bf16  g_w2h  [(size_t)LAYERS * 512 * HIDDEN];
__device__ bf16  g_w2l  [(size_t)LAYERS * 512 * HIDDEN];
__device__ float g_bqkv [LAYERS * QKV6];
__device__ float g_bo   [LAYERS * HIDDEN];
// CSR scratch
__device__ int   g_cnt    [NV];
__device__ int   g_rowptrL[NV + 1];
__device__ int   g_esrcL  [N_EDGES];
__device__ int   g_esrcE  [LAYERS * E_EXP];
__device__ int   g_cursor [NV];
__device__ int   g_bsum   [32];
// virtual-node reduction scratch
#define VN_SLOTS 512
__device__ float g_vnacc2[VN_SLOTS * HIDDEN];
__device__ float g_vnsum2[VN_SLOTS * HEADS];

// ---------------------------------------------------------------------------
// Helpers
// ---------------------------------------------------------------------------
__device__ __forceinline__ void split2(float x, bf16& h, bf16& l) {
    h = __float2bfloat16_rn(x);
    l = __float2bfloat16_rn(x - __bfloat162float(h));
}

// ---------------------------------------------------------------------------
// Utility / setup kernels
// ---------------------------------------------------------------------------
__global__ void k_zero_i(int* p, int n) {
    int i = blockIdx.x * blockDim.x + threadIdx.x;
    if (i < n) p[i] = 0;
}
__global__ void k_build_xv(const float4* __restrict__ x, float4* __restrict__ xv) {
    size_t i = (size_t)blockIdx.x * blockDim.x + threadIdx.x;
    size_t tot = (size_t)NV * HIDDEN / 4;
    size_t lim = (size_t)N_NODES * HIDDEN / 4;
    if (i < tot) xv[i] = (i < lim) ? x[i] : make_float4(0.f, 0.f, 0.f, 0.f);
}

// Pack + pre-split all weights once.
__global__ void k_pack_all(
    const float* __restrict__ lq_w, const float* __restrict__ lk_w,
    const float* __restrict__ lv_w, const float* __restrict__ eq_w,
    const float* __restrict__ ek_w, const float* __restrict__ ev_w,
    const float* __restrict__ lq_b, const float* __restrict__ lk_b,
    const float* __restrict__ lv_b, const float* __restrict__ eq_b,
    const float* __restrict__ ek_b, const float* __restrict__ ev_b,
    const float* __restrict__ lo_w, const float* __restrict__ eo_w,
    const float* __restrict__ lo_b, const float* __restrict__ eo_b,
    const float* __restrict__ w1, const float* __restrict__ w2,
    bf16* __restrict__ wqkvh, bf16* __restrict__ wqkvl,
    bf16* __restrict__ woh,  bf16* __restrict__ wol,
    bf16* __restrict__ w1h,  bf16* __restrict__ w1l,
    bf16* __restrict__ w2h,  bf16* __restrict__ w2l,
    float* __restrict__ bqkv, float* __restrict__ bo)
{
    int i = blockIdx.x * blockDim.x + threadIdx.x;
    const int NQ = LAYERS * HIDDEN * QKV6;
    const int NO = LAYERS * 256 * HIDDEN;
    const int NW = LAYERS * HIDDEN * 512;
    if (i < NQ) {
        int l = i / (HIDDEN * QKV6);
        int r = i % (HIDDEN * QKV6);
        int k = r / QKV6, n = r % QKV6;
        int sel = n >> 7, c = n & 127;
        const float* w[6] = {lq_w, lk_w, lv_w, eq_w, ek_w, ev_w};
        float v = w[sel][(size_t)l * HIDDEN * HIDDEN + k * HIDDEN + c];
        split2(v, wqkvh[i], wqkvl[i]);
    }
    if (i < NO) {
        int l = i / (256 * HIDDEN);
        int r = i % (256 * HIDDEN);
        int k = r / HIDDEN, n = r % HIDDEN;
        float v = (k < 128)
            ? lo_w[(size_t)l * HIDDEN * HIDDEN + k * HIDDEN + n]
            : eo_w[(size_t)l * HIDDEN * HIDDEN + (k - 128) * HIDDEN + n];
        split2(v, woh[i], wol[i]);
    }
    if (i < NW) {
        split2(w1[i], w1h[i], w1l[i]);
        split2(w2[i], w2h[i], w2l[i]);
    }
    if (i < LAYERS * QKV6) {
        int l = i / QKV6, n = i % QKV6;
        int sel = n >> 7, c = n & 127;
        const float* b[6] = {lq_b, lk_b, lv_b, eq_b, ek_b, ev_b};
        bqkv[i] = b[sel][l * HIDDEN + c];
    }
    if (i < LAYERS * HIDDEN) {
        int l = i / HIDDEN, n = i % HIDDEN;
        bo[i] = lo_b[l * HIDDEN + n] + eo_b[l * HIDDEN + n];
    }
}

// ---------------------------------------------------------------------------
// Local CSR build
// ---------------------------------------------------------------------------
__global__ void k_hist(const int* __restrict__ dst, int E, int* __restrict__ cnt) {
    int e = blockIdx.x * blockDim.x + threadIdx.x;
    if (e < E) atomicAdd(&cnt[dst[e]], 1);
}
__global__ void k_scan1(const int* __restrict__ cnt, int* __restrict__ rowptr,
                        int* __restrict__ bsum, int n) {
    __shared__ int wsum[32];
    const int tid = threadIdx.x, lane = tid & 31, wid = tid >> 5;
    int i = blockIdx.x * 1024 + tid;
    int x = (i < n) ? cnt[i] : 0;
    #pragma unroll
    for (int off = 1; off < 32; off <<= 1) {
        int t = __shfl_up_sync(0xffffffffu, x, off);
        if (lane >= off) x += t;
    }
    if (lane == 31) wsum[wid] = x;
    __syncthreads();
    if (wid == 0) {
        int y = wsum[lane];
        #pragma unroll
        for (int off = 1; off < 32; off <<= 1) {
            int t = __shfl_up_sync(0xffffffffu, y, off);
            if (lane >= off) y += t;
        }
        wsum[lane] = y;
    }
    __syncthreads();
    int total = x + ((wid > 0) ? wsum[wid - 1] : 0);
    if (i < n) rowptr[i + 1] = total;
    if (tid == 1023) bsum[blockIdx.x] = total;
}
__global__ void k_scan2(int* __restrict__ bsum, int nb) {
    int lane = threadIdx.x;
    int v = (lane < nb) ? bsum[lane] : 0;
    int orig = v;
    #pragma unroll
    for (int off = 1; off < 32; off <<= 1) {
        int t = __shfl_up_sync(0xffffffffu, v, off);
        if (lane >= off) v += t;
    }
    if (lane < nb) bsum[lane] = v - orig;
}
__global__ void k_scan3(int* __restrict__ rowptr, const int* __restrict__ bsum,
                        const int* __restrict__ cnt, int* __restrict__ cursor, int n) {
    int i = blockIdx.x * blockDim.x + threadIdx.x;
    if (i < n) {
        int v = rowptr[i + 1] + bsum[i >> 10];
        rowptr[i + 1] = v;
        cursor[i] = v - cnt[i];
        if (i == 0) rowptr[0] = 0;
    }
}
__global__ void k_scatter(const int* __restrict__ src, const int* __restrict__ dst,
                          int E, int* __restrict__ cursor, int* __restrict__ esrc) {
    int e = blockIdx.x * blockDim.x + threadIdx.x;
    if (e < E) {
        int pos = atomicAdd(&cursor[dst[e]], 1);
        esrc[pos] = src[e];
    }
}
__global__ void k_build_exp_all(const int* __restrict__ ee, int* __restrict__ esrc) {
    int e = blockIdx.x * blockDim.x + threadIdx.x;
    if (e < LAYERS * E_EXP) {
        int l = e / E_EXP, r = e % E_EXP;
        int g = r / NV;
        int src = ee[(size_t)l * 2 * E_EXP + r];
        int dst = ee[(size_t)l * 2 * E_EXP + E_EXP + r];
        esrc[(size_t)l * E_EXP + dst * 4 + g] = src;
    }
}

// ---------------------------------------------------------------------------
// Common GEMM pieces
// ---------------------------------------------------------------------------
#define BM 128
#define BN 128
#define BK 32
#define APAD 8
#define BPAD 8

__device__ __forceinline__ void ldsm_x4(uint32_t* r, const void* p) {
    uint32_t a = (uint32_t)__cvta_generic_to_shared(p);
    asm volatile("ldmatrix.sync.aligned.m8n8.x4.shared.b16 {%0,%1,%2,%3}, [%4];"
                 : "=r"(r[0]), "=r"(r[1]), "=r"(r[2]), "=r"(r[3]) : "r"(a));
}
__device__ __forceinline__ void ldsm_x4t(uint32_t* r, const void* p) {
    uint32_t a = (uint32_t)__cvta_generic_to_shared(p);
    asm volatile("ldmatrix.sync.aligned.m8n8.x4.trans.shared.b16 {%0,%1,%2,%3}, [%4];"
                 : "=r"(r[0]), "=r"(r[1]), "=r"(r[2]), "=r"(r[3]) : "r"(a));
}
__device__ __forceinline__ void mma_bf16(float* c, const uint32_t* a, const uint32_t* b) {
    asm volatile("mma.sync.aligned.m16n8k16.row.col.f32.bf16.bf16.f32 "
                 "{%0,%1,%2,%3}, {%4,%5,%6,%7}, {%8,%9}, {%0,%1,%2,%3};"
                 : "+f"(c[0]), "+f"(c[1]), "+f"(c[2]), "+f"(c[3])
                 : "r"(a[0]), "r"(a[1]), "r"(a[2]), "r"(a[3]), "r"(b[0]), "r"(b[1]));
}

// Shared BM=128 mainloop (macro so the qkv clone stays byte-identical)
#define GEMM128_MAINLOOP()                                                       \
    for (int k0 = 0; k0 < K; k0 += BK) {                                         \
        _Pragma("unroll")                                                        \
        for (int p = 0; p < 4; p++) {                                            \
            int r = ar0 + p * 32;                                                \
            float4 v = make_float4(0.f, 0.f, 0.f, 0.f);                          \
            if (bm + r < M) v = *(const float4*)(A + (size_t)(bm + r) * K + k0 + ac); \
            bf16 h, l;                                                           \
            split2(v.x, h, l); Ahs[r][ac + 0] = h; Als[r][ac + 0] = l;           \
            split2(v.y, h, l); Ahs[r][ac + 1] = h; Als[r][ac + 1] = l;           \
            split2(v.z, h, l); Ahs[r][ac + 2] = h; Als[r][ac + 2] = l;           \
            split2(v.w, h, l); Ahs[r][ac + 3] = h; Als[r][ac + 3] = l;           \
        }                                                                        \
        _Pragma("unroll")                                                        \
        for (int p = 0; p < 2; p++) {                                            \
            int r = bbr + p * 16;                                                \
            uint4 vh = *(const uint4*)(Bh + (size_t)(k0 + r) * N + bn + bbc);    \
            uint4 vl = *(const uint4*)(Bl + (size_t)(k0 + r) * N + bn + bbc);    \
            *(uint4*)&Bhs[r][bbc] = vh;                                          \
            *(uint4*)&Bls[r][bbc] = vl;                                          \
        }                                                                        \
        __syncthreads();                                                         \
        _Pragma("unroll")                                                        \
        for (int ks = 0; ks < 2; ks++) {                                         \
            uint32_t ahi[2][4], alo[2][4], bhi[8][2], blo[8][2];                 \
            _Pragma("unroll")                                                    \
            for (int mt = 0; mt < 2; mt++) {                                     \
                const int rr = wm * 32 + mt * 16 + (lane & 15);                  \
                const int cc = ks * 16 + ((lane >> 4) << 3);                     \
                ldsm_x4(ahi[mt], &Ahs[rr][cc]);                                  \
                ldsm_x4(alo[mt], &Als[rr][cc]);                                  \
            }                                                                    \
            _Pragma("unroll")                                                    \
            for (int nt = 0; nt < 4; nt++) {                                     \
                const int rr = ks * 16 + (lane & 15);                            \
                const int cc = wn * 64 + nt * 16 + ((lane >> 4) << 3);           \
                uint32_t th[4], tl[4];                                           \
                ldsm_x4t(th, &Bhs[rr][cc]);                                      \
                ldsm_x4t(tl, &Bls[rr][cc]);                                      \
                bhi[nt * 2][0] = th[0]; bhi[nt * 2][1] = th[1];                  \
                bhi[nt * 2 + 1][0] = th[2]; bhi[nt * 2 + 1][1] = th[3];          \
                blo[nt * 2][0] = tl[0]; blo[nt * 2][1] = tl[1];                  \
                blo[nt * 2 + 1][0] = tl[2]; blo[nt * 2 + 1][1] = tl[3];          \
            }                                                                    \
            _Pragma("unroll")                                                    \
            for (int mt = 0; mt < 2; mt++)                                       \
                _Pragma("unroll")                                                \
                for (int nb = 0; nb < 8; nb++) {                                 \
                    mma_bf16(acc[mt][nb], ahi[mt], bhi[nb]);                     \
                    mma_bf16(acc[mt][nb], ahi[mt], blo[nb]);                     \
                    mma_bf16(acc[mt][nb], alo[mt], bhi[nb]);                     \
                }                                                                \
        }                                                                        \
        __syncthreads();                                                         \
    }

// ---------------------------------------------------------------------------
// BM=128 GEMM for FFN1 (mode 2 gelu -> Ch? no: plain) and generic C=r/gelu
// ---------------------------------------------------------------------------
__global__ __launch_bounds__(256) void k_hgemm(
    const float* __restrict__ A,
    const bf16* __restrict__ Bh, const bf16* __restrict__ Bl,
    const float* __restrict__ bias, float* __restrict__ C,
    int M, int N, int K, int mode)
{
    __shared__ __align__(16) bf16 Ahs[BM][BK + APAD];
    __shared__ __align__(16) bf16 Als[BM][BK + APAD];
    __shared__ __align__(16) bf16 Bhs[BK][BN + BPAD];
    __shared__ __align__(16) bf16 Bls[BK][BN + BPAD];

    const int bm = blockIdx.y * BM;
    const int bn = blockIdx.x * BN;
    const int tid = threadIdx.x;
    const int lane = tid & 31;
    const int w = tid >> 5;
    const int wm = w & 3;
    const int wn = w >> 2;

    const int ar0 = tid >> 3;
    const int ac  = (tid & 7) << 2;
    const int bbr = tid >> 4;
    const int bbc = (tid & 15) << 3;

    float acc[2][8][4];
    #pragma unroll
    for (int i = 0; i < 2; i++)
        #pragma unroll
        for (int j = 0; j < 8; j++)
            #pragma unroll
            for (int t = 0; t < 4; t++) acc[i][j][t] = 0.0f;

    GEMM128_MAINLOOP()

    const int g = lane >> 2;
    const int t4 = lane & 3;
    #pragma unroll
    for (int mt = 0; mt < 2; mt++) {
        #pragma unroll
        for (int nb = 0; nb < 8; nb++) {
            int col = bn + wn * 64 + nb * 8 + t4 * 2;
            float b0 = bias[col], b1 = bias[col + 1];
            #pragma unroll
            for (int half = 0; half < 2; half++) {
                int row = bm + wm * 32 + mt * 16 + g + half * 8;
                if (row >= M) continue;
                float v0 = acc[mt][nb][half * 2 + 0] + b0;
                float v1 = acc[mt][nb][half * 2 + 1] + b1;
                if (mode == 2) {
                    v0 = 0.5f * v0 * (1.0f + erff(v0 * 0.70710678118654752440f));
                    v1 = 0.5f * v1 * (1.0f + erff(v1 * 0.70710678118654752440f));
                }
                *(float2*)(C + (size_t)row * N + col) = make_float2(v0, v1);
            }
        }
    }
}

// ---------------------------------------------------------------------------
// QKV clone: C = r (fp32) + also emit k-blocks (cols 128-255, 512-639)
// as bf16 into kbuf[NV][256] ([local k | exp k]).
// ---------------------------------------------------------------------------
__global__ __launch_bounds__(256) void k_hgemm_qkv(
    const float* __restrict__ A,
    const bf16* __restrict__ Bh, const bf16* __restrict__ Bl,
    const float* __restrict__ bias, float* __restrict__ C,
    bf16* __restrict__ kbuf,
    int M, int N, int K)
{
    __shared__ __align__(16) bf16 Ahs[BM][BK + APAD];
    __shared__ __align__(16) bf16 Als[BM][BK + APAD];
    __shared__ __align__(16) bf16 Bhs[BK][BN + BPAD];
    __shared__ __align__(16) bf16 Bls[BK][BN + BPAD];

    const int bm = blockIdx.y * BM;
    const int bn = blockIdx.x * BN;
    const int tid = threadIdx.x;
    const int lane = tid & 31;
    const int w = tid >> 5;
    const int wm = w & 3;
    const int wn = w >> 2;

    const int ar0 = tid >> 3;
    const int ac  = (tid & 7) << 2;
    const int bbr = tid >> 4;
    const int bbc = (tid & 15) << 3;

    float acc[2][8][4];
    #pragma unroll
    for (int i = 0; i < 2; i++)
        #pragma unroll
        for (int j = 0; j < 8; j++)
            #pragma unroll
            for (int t = 0; t < 4; t++) acc[i][j][t] = 0.0f;

    GEMM128_MAINLOOP()

    const int g = lane >> 2;
    const int t4 = lane & 3;
    #pragma unroll
    for (int mt = 0; mt < 2; mt++) {
        #pragma unroll
        for (int nb = 0; nb < 8; nb++) {
            int col = bn + wn * 64 + nb * 8 + t4 * 2;
            float b0 = bias[col], b1 = bias[col + 1];
            int blk = col >> 7;                       // 0..5 (constant per nb)
            bool isK = (blk == 1) || (blk == 4);
            int kcol = (blk == 1) ? (col - 128) : (col - 512 + 128);
            #pragma unroll
            for (int half = 0; half < 2; half++) {
                int row = bm + wm * 32 + mt * 16 + g + half * 8;
                if (row >= M) continue;
                float v0 = acc[mt][nb][half * 2 + 0] + b0;
                float v1 = acc[mt][nb][half * 2 + 1] + b1;
                *(float2*)(C + (size_t)row * N + col) = make_float2(v0, v1);
                if (isK)
                    *(bf162*)(kbuf + (size_t)row * 256 + kcol) =
                        __floats2bfloat162_rn(v0, v1);
            }
        }
    }
}

// ---------------------------------------------------------------------------
// BM=64 x BN=128 GEMM variants for N==128 (o-proj LN, FFN2)
// ---------------------------------------------------------------------------
#define BM64 64
#define VN_BLOCK (N_NODES / BM64)   // block y index owning row N_NODES (312)

#define GEMM64_MAINLOOP()                                                        \
    for (int k0 = 0; k0 < K; k0 += BK) {                                         \
        _Pragma("unroll")                                                        \
        for (int p = 0; p < 2; p++) {                                            \
            int r = ar0 + p * 32;                                                \
            float4 v = make_float4(0.f, 0.f, 0.f, 0.f);                          \
            if (bm + r < M) v = *(const float4*)(A + (size_t)(bm + r) * K + k0 + ac); \
            bf16 h, l;                                                           \
            split2(v.x, h, l); Ahs[r][ac + 0] = h; Als[r][ac + 0] = l;           \
            split2(v.y, h, l); Ahs[r][ac + 1] = h; Als[r][ac + 1] = l;           \
            split2(v.z, h, l); Ahs[r][ac + 2] = h; Als[r][ac + 2] = l;           \
            split2(v.w, h, l); Ahs[r][ac + 3] = h; Als[r][ac + 3] = l;           \
        }                                                                        \
        _Pragma("unroll")                                                        \
        for (int p = 0; p < 2; p++) {                                            \
            int r = bbr + p * 16;                                                \
            uint4 vh = *(const uint4*)(Bh + (size_t)(k0 + r) * 128 + bbc);       \
            uint4 vl = *(const uint4*)(Bl + (size_t)(k0 + r) * 128 + bbc);       \
            *(uint4*)&Bhs[r][bbc] = vh;                                          \
            *(uint4*)&Bls[r][bbc] = vl;                                          \
        }                                                                        \
        __syncthreads();                                                         \
        _Pragma("unroll")                                                        \
        for (int ks = 0; ks < 2; ks++) {                                         \
            uint32_t ahi[2][4], alo[2][4], bhi[4][2], blo[4][2];                 \
            _Pragma("unroll")                                                    \
            for (int mt = 0; mt < 2; mt++) {                                     \
                const int rr = wm * 32 + mt * 16 + (lane & 15);                  \
                const int cc = ks * 16 + ((lane >> 4) << 3);                     \
                ldsm_x4(ahi[mt], &Ahs[rr][cc]);                                  \
                ldsm_x4(alo[mt], &Als[rr][cc]);                                  \
            }                                                                    \
            _Pragma("unroll")                                                    \
            for (int nt = 0; nt < 2; nt++) {                                     \
                const int rr = ks * 16 + (lane & 15);                            \
                const int cc = wn * 32 + nt * 16 + ((lane >> 4) << 3);           \
                uint32_t th[4], tl[4];                                           \
                ldsm_x4t(th, &Bhs[rr][cc]);                                      \
                ldsm_x4t(tl, &Bls[rr][cc]);                                      \
                bhi[nt * 2][0] = th[0]; bhi[nt * 2][1] = th[1];                  \
                bhi[nt * 2 + 1][0] = th[2]; bhi[nt * 2 + 1][1] = th[3];          \
                blo[nt * 2][0] = tl[0]; blo[nt * 2][1] = tl[1];                  \
                blo[nt * 2 + 1][0] = tl[2]; blo[nt * 2 + 1][1] = tl[3];          \
            }                                                                    \
            _Pragma("unroll")                                                    \
            for (int mt = 0; mt < 2; mt++)                                       \
                _Pragma("unroll")                                                \
                for (int nb = 0; nb < 4; nb++) {                                 \
                    mma_bf16(acc[mt][nb], ahi[mt], bhi[nb]);                     \
                    mma_bf16(acc[mt][nb], ahi[mt], blo[nb]);                     \
                    mma_bf16(acc[mt][nb], alo[mt], bhi[nb]);                     \
                }                                                                \
        }                                                                        \
        __syncthreads();                                                         \
    }

// FFN2 variant: C += r (+ out2 rows < N_NODES).   N == 128.
__global__ __launch_bounds__(256) void k_hgemm64_acc(
    const float* __restrict__ A,
    const bf16* __restrict__ Bh, const bf16* __restrict__ Bl,
    const float* __restrict__ bias, float* __restrict__ C,
    float* __restrict__ out2, int M, int K)
{
    __shared__ __align__(16) bf16 Ahs[BM64][BK + APAD];
    __shared__ __align__(16) bf16 Als[BM64][BK + APAD];
    __shared__ __align__(16) bf16 Bhs[BK][BN + BPAD];
    __shared__ __align__(16) bf16 Bls[BK][BN + BPAD];

    const int bm = blockIdx.y * BM64;
    const int tid = threadIdx.x;
    const int lane = tid & 31;
    const int w = tid >> 5;
    const int wm = w & 1;
    const int wn = w >> 1;

    const int ar0 = tid >> 3;
    const int ac  = (tid & 7) << 2;
    const int bbr = tid >> 4;
    const int bbc = (tid & 15) << 3;

    float acc[2][4][4];
    #pragma unroll
    for (int i = 0; i < 2; i++)
        #pragma unroll
        for (int j = 0; j < 4; j++)
            #pragma unroll
            for (int t = 0; t < 4; t++) acc[i][j][t] = 0.0f;

    GEMM64_MAINLOOP()

    const int g = lane >> 2;
    const int t4 = lane & 3;
    #pragma unroll
    for (int mt = 0; mt < 2; mt++) {
        #pragma unroll
        for (int nb = 0; nb < 4; nb++) {
            int col = wn * 32 + nb * 8 + t4 * 2;
            float b0 = bias[col], b1 = bias[col + 1];
            #pragma unroll
            for (int half = 0; half < 2; half++) {
                int row = bm + wm * 32 + mt * 16 + g + half * 8;
                if (row >= M) continue;
                float* cp = C + (size_t)row * 128 + col;
                float2 old = *(const float2*)cp;
                float v0 = acc[mt][nb][half * 2 + 0] + b0 + old.x;
                float v1 = acc[mt][nb][half * 2 + 1] + b1 + old.y;
                *(float2*)cp = make_float2(v0, v1);
                if (out2 && row < N_NODES)
                    *(float2*)(out2 + (size_t)row * 128 + col) = make_float2(v0, v1);
            }
        }
    }
}

// o-proj variant: xv = LN(xv + r).   N == 128.
// Block VN_BLOCK finalizes the virtual-node row of agg in its prologue.
__global__ __launch_bounds__(256) void k_hgemm64_ln(
    const float* __restrict__ A,
    float* __restrict__ aggw,
    const float* __restrict__ vnacc2, const float* __restrict__ vnsum2,
    const bf16* __restrict__ Bh, const bf16* __restrict__ Bl,
    const float* __restrict__ bias, float* __restrict__ C,
    const float* __restrict__ lng, const float* __restrict__ lnb,
    int M, int K)
{
    __shared__ __align__(16) bf16 Ahs[BM64][BK + APAD];
    __shared__ __align__(16) bf16 Als[BM64][BK + APAD];
    __shared__ __align__(16) bf16 Bhs[BK][BN + BPAD];
    __shared__ __align__(16) bf16 Bls[BK][BN + BPAD];
    __shared__ float rsum[BM64][4], rsq[BM64][4];

    const int bm = blockIdx.y * BM64;
    const int tid = threadIdx.x;
    const int lane = tid & 31;
    const int w = tid >> 5;
    const int wm = w & 1;
    const int wn = w >> 1;

    const int ar0 = tid >> 3;
    const int ac  = (tid & 7) << 2;
    const int bbr = tid >> 4;
    const int bbc = (tid & 15) << 3;

    if (blockIdx.y == VN_BLOCK) {
        if (tid < HIDDEN) {
            int head = tid >> 4;
            float accv = 0.0f, ssum = 0.0f;
            for (int s = 0; s < VN_SLOTS; s++) {
                accv += vnacc2[(size_t)s * HIDDEN + tid];
                ssum += vnsum2[s * HEADS + head];
            }
            aggw[(size_t)N_NODES * 256 + tid] = accv / (ssum + 1e-16f);
        }
        __syncthreads();
    }

    float acc[2][4][4];
    #pragma unroll
    for (int i = 0; i < 2; i++)
        #pragma unroll
        for (int j = 0; j < 4; j++)
            #pragma unroll
            for (int t = 0; t < 4; t++) acc[i][j][t] = 0.0f;

    GEMM64_MAINLOOP()

    const int g = lane >> 2;
    const int t4 = lane & 3;

    // bias + residual
    #pragma unroll
    for (int mt = 0; mt < 2; mt++) {
        #pragma unroll
        for (int nb = 0; nb < 4; nb++) {
            int col = wn * 32 + nb * 8 + t4 * 2;
            float b0 = bias[col], b1 = bias[col + 1];
            #pragma unroll
            for (int half = 0; half < 2; half++) {
                int row = bm + wm * 32 + mt * 16 + g + half * 8;
                float v0 = acc[mt][nb][half * 2 + 0] + b0;
                float v1 = acc[mt][nb][half * 2 + 1] + b1;
                if (row < M) {
                    float2 old = *(const float2*)(C + (size_t)row * 128 + col);
                    v0 += old.x; v1 += old.y;
                }
                acc[mt][nb][half * 2 + 0] = v0;
                acc[mt][nb][half * 2 + 1] = v1;
            }
        }
    }

    // per-row partial sums across wn = 0..3
    #pragma unroll
    for (int mt = 0; mt < 2; mt++) {
        #pragma unroll
        for (int half = 0; half < 2; half++) {
            float s = 0.0f, q = 0.0f;
            #pragma unroll
            for (int nb = 0; nb < 4; nb++) {
                float v0 = acc[mt][nb][half * 2 + 0];
                float v1 = acc[mt][nb][half * 2 + 1];
                s += v0 + v1;
                q += v0 * v0 + v1 * v1;
            }
            s += __shfl_xor_sync(0xffffffffu, s, 1);
            s += __shfl_xor_sync(0xffffffffu, s, 2);
            q += __shfl_xor_sync(0xffffffffu, q, 1);
            q += __shfl_xor_sync(0xffffffffu, q, 2);
            if (t4 == 0) {
                int rl = wm * 32 + mt * 16 + g + half * 8;
                rsum[rl][wn] = s;
                rsq[rl][wn] = q;
            }
        }
    }
    __syncthreads();

    #pragma unroll
    for (int mt = 0; mt < 2; mt++) {
        #pragma unroll
        for (int nb = 0; nb < 4; nb++) {
            int col = wn * 32 + nb * 8 + t4 * 2;
            float g0 = lng[col], g1 = lng[col + 1];
            float e0 = lnb[col], e1 = lnb[col + 1];
            #pragma unroll
            for (int half = 0; half < 2; half++) {
                int rl = wm * 32 + mt * 16 + g + half * 8;
                int row = bm + rl;
                if (row >= M) continue;
                float mu  = (rsum[rl][0] + rsum[rl][1] + rsum[rl][2] + rsum[rl][3])
                            * (1.0f / HIDDEN);
                float var = (rsq[rl][0] + rsq[rl][1] + rsq[rl][2] + rsq[rl][3])
                            * (1.0f / HIDDEN) - mu * mu;
                float inv = rsqrtf(var + 1e-5f);
                float v0 = (acc[mt][nb][half * 2 + 0] - mu) * inv * g0 + e0;
                float v1 = (acc[mt][nb][half * 2 + 1] - mu) * inv * g1 + e1;
                *(float2*)(C + (size_t)row * 128 + col) = make_float2(v0, v1);
            }
        }
    }
}

// ---------------------------------------------------------------------------
// Combined gather: warps [0,N_NODES) local, rest expander.
// k now read from compact bf16 kbuf (halves random k traffic).
// ---------------------------------------------------------------------------
__global__ void k_gather_both(const float* __restrict__ qkv,
                              const bf16* __restrict__ kbuf,
                              float* __restrict__ agg,
                              const int* __restrict__ rowptr,
                              const int* __restrict__ esrcL,
                              const int* __restrict__ esrcE)
{
    int wrp = (blockIdx.x * blockDim.x + threadIdx.x) >> 5;
    int lane = threadIdx.x & 31;
    const int total = N_NODES + NV;
    if (wrp >= total) return;

    const bool isExp = (wrp >= N_NODES);
    const int d = isExp ? (wrp - N_NODES) : wrp;
    const int qoff = isExp ? 384 : 0;
    const int koff = isExp ? 128 : 0;
    const int voff = qoff + 256;
    const int* esrc = isExp ? esrcE : esrcL;

    float4 qd = *(const float4*)(qkv + (size_t)d * QKV6 + qoff + lane * 4);
    float4 vacc = make_float4(0.f, 0.f, 0.f, 0.f);
    float ssum = 0.0f;

    int beg, end, addVN;
    if (isExp) { beg = d * 4;      end = beg + 4;       addVN = 0; }
    else       { beg = rowptr[d];  end = rowptr[d + 1]; addVN = 1; }

    for (int e = beg; e <= end; e++) {
        int s;
        if (e < end) s = esrc[e];
        else if (addVN) s = N_NODES;
        else break;
        uint2 kr = *(const uint2*)(kbuf + (size_t)s * 256 + koff + lane * 4);
        float2 k01 = __bfloat1622float2(*(const bf162*)&kr.x);
        float2 k23 = __bfloat1622float2(*(const bf162*)&kr.y);
        float dp = qd.x * k01.x + qd.y * k01.y + qd.z * k23.x + qd.w * k23.y;
        dp += __shfl_xor_sync(0xffffffffu, dp, 1);
        dp += __shfl_xor_sync(0xffffffffu, dp, 2);
        float ex = __expf(dp * 0.25f);
        float4 va = *(const float4*)(qkv + (size_t)s * QKV6 + voff + lane * 4);
        vacc.x = fmaf(ex, va.x, vacc.x);
        vacc.y = fmaf(ex, va.y, vacc.y);
        vacc.z = fmaf(ex, va.z, vacc.z);
        vacc.w = fmaf(ex, va.w, vacc.w);
        ssum += ex;
    }
    float inv = 1.0f / (ssum + 1e-16f);
    *(float4*)(agg + (size_t)d * 256 + (isExp ? 128 : 0) + lane * 4) =
        make_float4(vacc.x * inv, vacc.y * inv, vacc.z * inv, vacc.w * inv);
}

// ---------------------------------------------------------------------------
// Virtual node partials (k from kbuf)
// ---------------------------------------------------------------------------
__global__ void k_vn_partial(const float* __restrict__ qkv,
                             const bf16* __restrict__ kbuf,
                             float* __restrict__ vnacc2, float* __restrict__ vnsum2)
{
    int wrp = (blockIdx.x * blockDim.x + threadIdx.x) >> 5;
    int lane = threadIdx.x & 31;

    float4 qd = *(const float4*)(qkv + (size_t)N_NODES * QKV6 + lane * 4);
    float4 vacc = make_float4(0.f, 0.f, 0.f, 0.f);
    float ssum = 0.0f;

    for (int s = wrp; s < N_NODES; s += VN_SLOTS) {
        uint2 kr = *(const uint2*)(kbuf + (size_t)s * 256 + lane * 4);
        float2 k01 = __bfloat1622float2(*(const bf162*)&kr.x);
        float2 k23 = __bfloat1622float2(*(const bf162*)&kr.y);
        float dp = qd.x * k01.x + qd.y * k01.y + qd.z * k23.x + qd.w * k23.y;
        dp += __shfl_xor_sync(0xffffffffu, dp, 1);
        dp += __shfl_xor_sync(0xffffffffu, dp, 2);
        float ex = __expf(dp * 0.25f);
        float4 va = *(const float4*)(qkv + (size_t)s * QKV6 + 256 + lane * 4);
        vacc.x = fmaf(ex, va.x, vacc.x);
        vacc.y = fmaf(ex, va.y, vacc.y);
        vacc.z = fmaf(ex, va.z, vacc.z);
        vacc.w = fmaf(ex, va.w, vacc.w);
        ssum += ex;
    }
    *(float4*)(vnacc2 + (size_t)wrp * HIDDEN + lane * 4) = vacc;
    if ((lane & 3) == 0) vnsum2[wrp * HEADS + (lane >> 2)] = ssum;
}

// ---------------------------------------------------------------------------
// Host-side orchestration
// ---------------------------------------------------------------------------
static inline dim3 grid1(size_t n, int bs) { return dim3((unsigned)((n + bs - 1) / bs)); }

extern "C" void kernel_launch(void* const* d_in, const int* in_sizes, int n_in,
                              void* d_out, int out_size)
{
    (void)n_in; (void)in_sizes; (void)out_size;
    const float* x         = (const float*)d_in[0];
    const int*   edge_idx  = (const int*)  d_in[1];
    const int*   exp_edges = (const int*)  d_in[2];
    const float* lq_w = (const float*)d_in[3];   const float* lq_b = (const float*)d_in[4];
    const float* lk_w = (const float*)d_in[5];   const float* lk_b = (const float*)d_in[6];
    const float* lv_w = (const float*)d_in[7];   const float* lv_b = (const float*)d_in[8];
    const float* lo_w = (const float*)d_in[9];   const float* lo_b = (const float*)d_in[10];
    const float* eq_w = (const float*)d_in[11];  const float* eq_b = (const float*)d_in[12];
    const float* ek_w = (const float*)d_in[13];  const float* ek_b = (const float*)d_in[14];
    const float* ev_w = (const float*)d_in[15];  const float* ev_b = (const float*)d_in[16];
    const float* eo_w = (const float*)d_in[17];  const float* eo_b = (const float*)d_in[18];
    const float* ln_g = (const float*)d_in[19];  const float* ln_b = (const float*)d_in[20];
    const float* ffn_w1 = (const float*)d_in[21]; const float* ffn_b1 = (const float*)d_in[22];
    const float* ffn_w2 = (const float*)d_in[23]; const float* ffn_b2 = (const float*)d_in[24];

    float *xv, *qkv, *agg, *h1, *bqkv, *bo, *vnacc2, *vnsum2;
    bf16 *kbuf, *wqkvh, *wqkvl, *woh, *wol, *w1h, *w1l, *w2h, *w2l;
    int *cnt, *rowptrL, *esrcL, *esrcE, *cursor, *bsum;
    cudaGetSymbolAddress((void**)&xv,      g_xv);
    cudaGetSymbolAddress((void**)&qkv,     g_qkv);
    cudaGetSymbolAddress((void**)&kbuf,    g_kbuf);
    cudaGetSymbolAddress((void**)&agg,     g_agg);
    cudaGetSymbolAddress((void**)&h1,      g_h1);
    cudaGetSymbolAddress((void**)&wqkvh,   g_wqkvh);
    cudaGetSymbolAddress((void**)&wqkvl,   g_wqkvl);
    cudaGetSymbolAddress((void**)&woh,     g_woh);
    cudaGetSymbolAddress((void**)&wol,     g_wol);
    cudaGetSymbolAddress((void**)&w1h,     g_w1h);
    cudaGetSymbolAddress((void**)&w1l,     g_w1l);
    cudaGetSymbolAddress((void**)&w2h,     g_w2h);
    cudaGetSymbolAddress((void**)&w2l,     g_w2l);
    cudaGetSymbolAddress((void**)&bqkv,    g_bqkv);
    cudaGetSymbolAddress((void**)&bo,      g_bo);
    cudaGetSymbolAddress((void**)&vnacc2,  g_vnacc2);
    cudaGetSymbolAddress((void**)&vnsum2,  g_vnsum2);
    cudaGetSymbolAddress((void**)&cnt,     g_cnt);
    cudaGetSymbolAddress((void**)&rowptrL, g_rowptrL);
    cudaGetSymbolAddress((void**)&esrcL,   g_esrcL);
    cudaGetSymbolAddress((void**)&esrcE,   g_esrcE);
    cudaGetSymbolAddress((void**)&cursor,  g_cursor);
    cudaGetSymbolAddress((void**)&bsum,    g_bsum);

    const size_t nvh = (size_t)NV * HIDDEN;

    // ---- setup ----
    k_build_xv<<<grid1(nvh / 4, 256), 256>>>((const float4*)x, (float4*)xv);
    k_zero_i<<<grid1(NV, 256), 256>>>(cnt, NV);
    k_hist<<<grid1(N_EDGES, 256), 256>>>(edge_idx + N_EDGES, N_EDGES, cnt);
    {
        int nblk = (NV + 1023) / 1024;
        k_scan1<<<nblk, 1024>>>(cnt, rowptrL, bsum, NV);
        k_scan2<<<1, 32>>>(bsum, nblk);
        k_scan3<<<grid1(NV, 256), 256>>>(rowptrL, bsum, cnt, cursor, NV);
    }
    k_scatter<<<grid1(N_EDGES, 256), 256>>>(edge_idx, edge_idx + N_EDGES, N_EDGES,
                                            cursor, esrcL);
    k_build_exp_all<<<grid1((size_t)LAYERS * E_EXP, 256), 256>>>(exp_edges, esrcE);
    k_pack_all<<<grid1((size_t)LAYERS * HIDDEN * QKV6, 256), 256>>>(
        lq_w, lk_w, lv_w, eq_w, ek_w, ev_w,
        lq_b, lk_b, lv_b, eq_b, ek_b, ev_b,
        lo_w, eo_w, lo_b, eo_b, ffn_w1, ffn_w2,
        wqkvh, wqkvl, woh, wol, w1h, w1l, w2h, w2l, bqkv, bo);

    // ---- layers ----
    for (int l = 0; l < LAYERS; l++) {
        // qkv = xv @ wqkv + b, also emits bf16 k-blocks into kbuf
        {
            dim3 gg(QKV6 / BN, (NV + BM - 1) / BM);
            k_hgemm_qkv<<<gg, 256>>>(xv, wqkvh + (size_t)l * HIDDEN * QKV6,
                                     wqkvl + (size_t)l * HIDDEN * QKV6,
                                     bqkv + l * QKV6, qkv, kbuf, NV, QKV6, HIDDEN);
        }

        // combined gather (local + expander) + vn partials
        k_gather_both<<<grid1((size_t)(N_NODES + NV) * 32, 256), 256>>>(
            qkv, kbuf, agg, rowptrL, esrcL, esrcE + (size_t)l * E_EXP);
        k_vn_partial<<<VN_SLOTS / 8, 256>>>(qkv, kbuf, vnacc2, vnsum2);

        // fused o-projection + residual + LN (vn-final folded into VN_BLOCK)
        {
            dim3 gg(1, (NV + BM64 - 1) / BM64);
            k_hgemm64_ln<<<gg, 256>>>(agg, agg, vnacc2, vnsum2,
                                      woh + (size_t)l * 256 * HIDDEN,
                                      wol + (size_t)l * 256 * HIDDEN, bo + l * HIDDEN,
                                      xv, ln_g + (size_t)l * HIDDEN,
                                      ln_b + (size_t)l * HIDDEN, NV, 256);
        }

        // FFN1: h1 = gelu(xv@w1+b1)
        {
            dim3 gg(512 / BN, (NV + BM - 1) / BM);
            k_hgemm<<<gg, 256>>>(xv, w1h + (size_t)l * HIDDEN * 512,
                                 w1l + (size_t)l * HIDDEN * 512, ffn_b1 + (size_t)l * 512,
                                 h1, NV, 512, HIDDEN, 2);
        }
        // FFN2: xv += h1@w2+b2 (last layer also writes d_out)
        {
            dim3 gg(1, (NV + BM64 - 1) / BM64);
            k_hgemm64_acc<<<gg, 256>>>(h1, w2h + (size_t)l * 512 * HIDDEN,
                                       w2l + (size_t)l * 512 * HIDDEN,
                                       ffn_b2 + (size_t)l * HIDDEN, xv,
                                       (l == LAYERS - 1) ? (float*)d_out : nullptr,
                                       NV, 512);
        }
    }
}

// round 16
// speedup vs baseline: 1.0814x; 1.0814x over previous
#include <cuda_runtime.h>
#include <cuda_bf16.h>
#include <math.h>
#include <stdint.h>

// ---------------------------------------------------------------------------
// Problem constants
// ---------------------------------------------------------------------------
#define N_NODES 20000
#define N_EDGES 320000
#define HIDDEN  128
#define HEADS   8
#define LAYERS  3
#define NV      (N_NODES + 1)
#define E_EXP   (NV * 4)                 // 80004 per layer
#define QKV6    (6 * HIDDEN)             // 768: lq|lk|lv|eq|ek|ev

typedef __nv_bfloat16  bf16;
typedef __nv_bfloat162 bf162;

// ---------------------------------------------------------------------------
// Scratch (device globals; no allocations)
// ---------------------------------------------------------------------------
__device__ float g_xv   [(size_t)NV * HIDDEN];
__device__ float g_qkv  [(size_t)NV * QKV6];
__device__ float g_agg  [(size_t)NV * 256];           // [local 128 | exp 128]
__device__ float g_h1   [(size_t)NV * 4 * HIDDEN];
// packed + PRE-SPLIT weights (B operands only)
__device__ bf16  g_wqkvh[(size_t)LAYERS * HIDDEN * QKV6];
__device__ bf16  g_wqkvl[(size_t)LAYERS * HIDDEN * QKV6];
__device__ bf16  g_woh  [(size_t)LAYERS * 256 * HIDDEN];
__device__ bf16  g_wol  [(size_t)LAYERS * 256 * HIDDEN];
__device__ bf16  g_w1h  [(size_t)LAYERS * HIDDEN * 512];
__device__ bf16  g_w1l  [(size_t)LAYERS * HIDDEN * 512];
__device__ bf16  g_w2h  [(size_t)LAYERS * 512 * HIDDEN];
__device__ bf16  g_w2l  [(size_t)LAYERS * 512 * HIDDEN];
__device__ float g_bqkv [LAYERS * QKV6];
__device__ float g_bo   [LAYERS * HIDDEN];
// CSR scratch
__device__ int   g_cnt    [NV];
__device__ int   g_rowptrL[NV + 1];
__device__ int   g_esrcL  [N_EDGES];
__device__ int   g_esrcE  [LAYERS * E_EXP];
__device__ int   g_cursor [NV];
__device__ int   g_bsum   [32];
// virtual-node reduction scratch
#define VN_SLOTS 512
__device__ float g_vnacc2[VN_SLOTS * HIDDEN];
__device__ float g_vnsum2[VN_SLOTS * HEADS];

// ---------------------------------------------------------------------------
// Helpers
// ---------------------------------------------------------------------------
__device__ __forceinline__ void split2(float x, bf16& h, bf16& l) {
    h = __float2bfloat16_rn(x);
    l = __float2bfloat16_rn(x - __bfloat162float(h));
}

// ---------------------------------------------------------------------------
// Utility / setup kernels
// ---------------------------------------------------------------------------
__global__ void k_zero_i(int* p, int n) {
    int i = blockIdx.x * blockDim.x + threadIdx.x;
    if (i < n) p[i] = 0;
}
__global__ void k_build_xv(const float4* __restrict__ x, float4* __restrict__ xv) {
    size_t i = (size_t)blockIdx.x * blockDim.x + threadIdx.x;
    size_t tot = (size_t)NV * HIDDEN / 4;
    size_t lim = (size_t)N_NODES * HIDDEN / 4;
    if (i < tot) xv[i] = (i < lim) ? x[i] : make_float4(0.f, 0.f, 0.f, 0.f);
}

// Pack + pre-split all weights once.
__global__ void k_pack_all(
    const float* __restrict__ lq_w, const float* __restrict__ lk_w,
    const float* __restrict__ lv_w, const float* __restrict__ eq_w,
    const float* __restrict__ ek_w, const float* __restrict__ ev_w,
    const float* __restrict__ lq_b, const float* __restrict__ lk_b,
    const float* __restrict__ lv_b, const float* __restrict__ eq_b,
    const float* __restrict__ ek_b, const float* __restrict__ ev_b,
    const float* __restrict__ lo_w, const float* __restrict__ eo_w,
    const float* __restrict__ lo_b, const float* __restrict__ eo_b,
    const float* __restrict__ w1, const float* __restrict__ w2,
    bf16* __restrict__ wqkvh, bf16* __restrict__ wqkvl,
    bf16* __restrict__ woh,  bf16* __restrict__ wol,
    bf16* __restrict__ w1h,  bf16* __restrict__ w1l,
    bf16* __restrict__ w2h,  bf16* __restrict__ w2l,
    float* __restrict__ bqkv, float* __restrict__ bo)
{
    int i = blockIdx.x * blockDim.x + threadIdx.x;
    const int NQ = LAYERS * HIDDEN * QKV6;
    const int NO = LAYERS * 256 * HIDDEN;
    const int NW = LAYERS * HIDDEN * 512;
    if (i < NQ) {
        int l = i / (HIDDEN * QKV6);
        int r = i % (HIDDEN * QKV6);
        int k = r / QKV6, n = r % QKV6;
        int sel = n >> 7, c = n & 127;
        const float* w[6] = {lq_w, lk_w, lv_w, eq_w, ek_w, ev_w};
        float v = w[sel][(size_t)l * HIDDEN * HIDDEN + k * HIDDEN + c];
        split2(v, wqkvh[i], wqkvl[i]);
    }
    if (i < NO) {
        int l = i / (256 * HIDDEN);
        int r = i % (256 * HIDDEN);
        int k = r / HIDDEN, n = r % HIDDEN;
        float v = (k < 128)
            ? lo_w[(size_t)l * HIDDEN * HIDDEN + k * HIDDEN + n]
            : eo_w[(size_t)l * HIDDEN * HIDDEN + (k - 128) * HIDDEN + n];
        split2(v, woh[i], wol[i]);
    }
    if (i < NW) {
        split2(w1[i], w1h[i], w1l[i]);
        split2(w2[i], w2h[i], w2l[i]);
    }
    if (i < LAYERS * QKV6) {
        int l = i / QKV6, n = i % QKV6;
        int sel = n >> 7, c = n & 127;
        const float* b[6] = {lq_b, lk_b, lv_b, eq_b, ek_b, ev_b};
        bqkv[i] = b[sel][l * HIDDEN + c];
    }
    if (i < LAYERS * HIDDEN) {
        int l = i / HIDDEN, n = i % HIDDEN;
        bo[i] = lo_b[l * HIDDEN + n] + eo_b[l * HIDDEN + n];
    }
}

// ---------------------------------------------------------------------------
// Local CSR build
// ---------------------------------------------------------------------------
__global__ void k_hist(const int* __restrict__ dst, int E, int* __restrict__ cnt) {
    int e = blockIdx.x * blockDim.x + threadIdx.x;
    if (e < E) atomicAdd(&cnt[dst[e]], 1);
}
__global__ void k_scan1(const int* __restrict__ cnt, int* __restrict__ rowptr,
                        int* __restrict__ bsum, int n) {
    __shared__ int wsum[32];
    const int tid = threadIdx.x, lane = tid & 31, wid = tid >> 5;
    int i = blockIdx.x * 1024 + tid;
    int x = (i < n) ? cnt[i] : 0;
    #pragma unroll
    for (int off = 1; off < 32; off <<= 1) {
        int t = __shfl_up_sync(0xffffffffu, x, off);
        if (lane >= off) x += t;
    }
    if (lane == 31) wsum[wid] = x;
    __syncthreads();
    if (wid == 0) {
        int y = wsum[lane];
        #pragma unroll
        for (int off = 1; off < 32; off <<= 1) {
            int t = __shfl_up_sync(0xffffffffu, y, off);
            if (lane >= off) y += t;
        }
        wsum[lane] = y;
    }
    __syncthreads();
    int total = x + ((wid > 0) ? wsum[wid - 1] : 0);
    if (i < n) rowptr[i + 1] = total;
    if (tid == 1023) bsum[blockIdx.x] = total;
}
__global__ void k_scan2(int* __restrict__ bsum, int nb) {
    int lane = threadIdx.x;
    int v = (lane < nb) ? bsum[lane] : 0;
    int orig = v;
    #pragma unroll
    for (int off = 1; off < 32; off <<= 1) {
        int t = __shfl_up_sync(0xffffffffu, v, off);
        if (lane >= off) v += t;
    }
    if (lane < nb) bsum[lane] = v - orig;
}
__global__ void k_scan3(int* __restrict__ rowptr, const int* __restrict__ bsum,
                        const int* __restrict__ cnt, int* __restrict__ cursor, int n) {
    int i = blockIdx.x * blockDim.x + threadIdx.x;
    if (i < n) {
        int v = rowptr[i + 1] + bsum[i >> 10];
        rowptr[i + 1] = v;
        cursor[i] = v - cnt[i];
        if (i == 0) rowptr[0] = 0;
    }
}
__global__ void k_scatter(const int* __restrict__ src, const int* __restrict__ dst,
                          int E, int* __restrict__ cursor, int* __restrict__ esrc) {
    int e = blockIdx.x * blockDim.x + threadIdx.x;
    if (e < E) {
        int pos = atomicAdd(&cursor[dst[e]], 1);
        esrc[pos] = src[e];
    }
}
__global__ void k_build_exp_all(const int* __restrict__ ee, int* __restrict__ esrc) {
    int e = blockIdx.x * blockDim.x + threadIdx.x;
    if (e < LAYERS * E_EXP) {
        int l = e / E_EXP, r = e % E_EXP;
        int g = r / NV;
        int src = ee[(size_t)l * 2 * E_EXP + r];
        int dst = ee[(size_t)l * 2 * E_EXP + E_EXP + r];
        esrc[(size_t)l * E_EXP + dst * 4 + g] = src;
    }
}

// ---------------------------------------------------------------------------
// Common GEMM pieces
// ---------------------------------------------------------------------------
#define BM 128
#define BN 128
#define BK 32
#define APAD 8
#define BPAD 8

__device__ __forceinline__ void ldsm_x4(uint32_t* r, const void* p) {
    uint32_t a = (uint32_t)__cvta_generic_to_shared(p);
    asm volatile("ldmatrix.sync.aligned.m8n8.x4.shared.b16 {%0,%1,%2,%3}, [%4];"
                 : "=r"(r[0]), "=r"(r[1]), "=r"(r[2]), "=r"(r[3]) : "r"(a));
}
__device__ __forceinline__ void ldsm_x4t(uint32_t* r, const void* p) {
    uint32_t a = (uint32_t)__cvta_generic_to_shared(p);
    asm volatile("ldmatrix.sync.aligned.m8n8.x4.trans.shared.b16 {%0,%1,%2,%3}, [%4];"
                 : "=r"(r[0]), "=r"(r[1]), "=r"(r[2]), "=r"(r[3]) : "r"(a));
}
__device__ __forceinline__ void mma_bf16(float* c, const uint32_t* a, const uint32_t* b) {
    asm volatile("mma.sync.aligned.m16n8k16.row.col.f32.bf16.bf16.f32 "
                 "{%0,%1,%2,%3}, {%4,%5,%6,%7}, {%8,%9}, {%0,%1,%2,%3};"
                 : "+f"(c[0]), "+f"(c[1]), "+f"(c[2]), "+f"(c[3])
                 : "r"(a[0]), "r"(a[1]), "r"(a[2]), "r"(a[3]), "r"(b[0]), "r"(b[1]));
}

// ---------------------------------------------------------------------------
// BM=128 GEMM: used for N=768 (qkv) and N=512 (FFN1)
//   mode 0: C = r;  2: C = gelu(r)
// ---------------------------------------------------------------------------
__global__ __launch_bounds__(256) void k_hgemm(
    const float* __restrict__ A,
    const bf16* __restrict__ Bh, const bf16* __restrict__ Bl,
    const float* __restrict__ bias, float* __restrict__ C,
    int M, int N, int K, int mode)
{
    __shared__ __align__(16) bf16 Ahs[BM][BK + APAD];
    __shared__ __align__(16) bf16 Als[BM][BK + APAD];
    __shared__ __align__(16) bf16 Bhs[BK][BN + BPAD];
    __shared__ __align__(16) bf16 Bls[BK][BN + BPAD];

    const int bm = blockIdx.y * BM;
    const int bn = blockIdx.x * BN;
    const int tid = threadIdx.x;
    const int lane = tid & 31;
    const int w = tid >> 5;
    const int wm = w & 3;
    const int wn = w >> 2;

    const int ar0 = tid >> 3;
    const int ac  = (tid & 7) << 2;
    const int bbr = tid >> 4;
    const int bbc = (tid & 15) << 3;

    float acc[2][8][4];
    #pragma unroll
    for (int i = 0; i < 2; i++)
        #pragma unroll
        for (int j = 0; j < 8; j++)
            #pragma unroll
            for (int t = 0; t < 4; t++) acc[i][j][t] = 0.0f;

    for (int k0 = 0; k0 < K; k0 += BK) {
        #pragma unroll
        for (int p = 0; p < 4; p++) {
            int r = ar0 + p * 32;
            float4 v = make_float4(0.f, 0.f, 0.f, 0.f);
            if (bm + r < M) v = *(const float4*)(A + (size_t)(bm + r) * K + k0 + ac);
            bf16 h, l;
            split2(v.x, h, l); Ahs[r][ac + 0] = h; Als[r][ac + 0] = l;
            split2(v.y, h, l); Ahs[r][ac + 1] = h; Als[r][ac + 1] = l;
            split2(v.z, h, l); Ahs[r][ac + 2] = h; Als[r][ac + 2] = l;
            split2(v.w, h, l); Ahs[r][ac + 3] = h; Als[r][ac + 3] = l;
        }
        #pragma unroll
        for (int p = 0; p < 2; p++) {
            int r = bbr + p * 16;
            uint4 vh = *(const uint4*)(Bh + (size_t)(k0 + r) * N + bn + bbc);
            uint4 vl = *(const uint4*)(Bl + (size_t)(k0 + r) * N + bn + bbc);
            *(uint4*)&Bhs[r][bbc] = vh;
            *(uint4*)&Bls[r][bbc] = vl;
        }
        __syncthreads();

        #pragma unroll
        for (int ks = 0; ks < 2; ks++) {
            uint32_t ahi[2][4], alo[2][4], bhi[8][2], blo[8][2];
            #pragma unroll
            for (int mt = 0; mt < 2; mt++) {
                const int rr = wm * 32 + mt * 16 + (lane & 15);
                const int cc = ks * 16 + ((lane >> 4) << 3);
                ldsm_x4(ahi[mt], &Ahs[rr][cc]);
                ldsm_x4(alo[mt], &Als[rr][cc]);
            }
            #pragma unroll
            for (int nt = 0; nt < 4; nt++) {
                const int rr = ks * 16 + (lane & 15);
                const int cc = wn * 64 + nt * 16 + ((lane >> 4) << 3);
                uint32_t th[4], tl[4];
                ldsm_x4t(th, &Bhs[rr][cc]);
                ldsm_x4t(tl, &Bls[rr][cc]);
                bhi[nt * 2][0] = th[0]; bhi[nt * 2][1] = th[1];
                bhi[nt * 2 + 1][0] = th[2]; bhi[nt * 2 + 1][1] = th[3];
                blo[nt * 2][0] = tl[0]; blo[nt * 2][1] = tl[1];
                blo[nt * 2 + 1][0] = tl[2]; blo[nt * 2 + 1][1] = tl[3];
            }
            #pragma unroll
            for (int mt = 0; mt < 2; mt++)
                #pragma unroll
                for (int nb = 0; nb < 8; nb++) {
                    mma_bf16(acc[mt][nb], ahi[mt], bhi[nb]);
                    mma_bf16(acc[mt][nb], ahi[mt], blo[nb]);
                    mma_bf16(acc[mt][nb], alo[mt], bhi[nb]);
                }
        }
        __syncthreads();
    }

    const int g = lane >> 2;
    const int t4 = lane & 3;
    #pragma unroll
    for (int mt = 0; mt < 2; mt++) {
        #pragma unroll
        for (int nb = 0; nb < 8; nb++) {
            int col = bn + wn * 64 + nb * 8 + t4 * 2;
            float b0 = bias[col], b1 = bias[col + 1];
            #pragma unroll
            for (int half = 0; half < 2; half++) {
                int row = bm + wm * 32 + mt * 16 + g + half * 8;
                if (row >= M) continue;
                float v0 = acc[mt][nb][half * 2 + 0] + b0;
                float v1 = acc[mt][nb][half * 2 + 1] + b1;
                if (mode == 2) {
                    v0 = 0.5f * v0 * (1.0f + erff(v0 * 0.70710678118654752440f));
                    v1 = 0.5f * v1 * (1.0f + erff(v1 * 0.70710678118654752440f));
                }
                *(float2*)(C + (size_t)row * N + col) = make_float2(v0, v1);
            }
        }
    }
}

// ---------------------------------------------------------------------------
// BM=64 x BN=128 GEMM variants for N==128 (o-proj LN, FFN2)
// ---------------------------------------------------------------------------
#define BM64 64
#define VN_BLOCK (N_NODES / BM64)   // block y index owning row N_NODES (312)

#define GEMM64_MAINLOOP()                                                        \
    for (int k0 = 0; k0 < K; k0 += BK) {                                         \
        _Pragma("unroll")                                                        \
        for (int p = 0; p < 2; p++) {                                            \
            int r = ar0 + p * 32;                                                \
            float4 v = make_float4(0.f, 0.f, 0.f, 0.f);                          \
            if (bm + r < M) v = *(const float4*)(A + (size_t)(bm + r) * K + k0 + ac); \
            bf16 h, l;                                                           \
            split2(v.x, h, l); Ahs[r][ac + 0] = h; Als[r][ac + 0] = l;           \
            split2(v.y, h, l); Ahs[r][ac + 1] = h; Als[r][ac + 1] = l;           \
            split2(v.z, h, l); Ahs[r][ac + 2] = h; Als[r][ac + 2] = l;           \
            split2(v.w, h, l); Ahs[r][ac + 3] = h; Als[r][ac + 3] = l;           \
        }                                                                        \
        _Pragma("unroll")                                                        \
        for (int p = 0; p < 2; p++) {                                            \
            int r = bbr + p * 16;                                                \
            uint4 vh = *(const uint4*)(Bh + (size_t)(k0 + r) * 128 + bbc);       \
            uint4 vl = *(const uint4*)(Bl + (size_t)(k0 + r) * 128 + bbc);       \
            *(uint4*)&Bhs[r][bbc] = vh;                                          \
            *(uint4*)&Bls[r][bbc] = vl;                                          \
        }                                                                        \
        __syncthreads();                                                         \
        _Pragma("unroll")                                                        \
        for (int ks = 0; ks < 2; ks++) {                                         \
            uint32_t ahi[2][4], alo[2][4], bhi[4][2], blo[4][2];                 \
            _Pragma("unroll")                                                    \
            for (int mt = 0; mt < 2; mt++) {                                     \
                const int rr = wm * 32 + mt * 16 + (lane & 15);                  \
                const int cc = ks * 16 + ((lane >> 4) << 3);                     \
                ldsm_x4(ahi[mt], &Ahs[rr][cc]);                                  \
                ldsm_x4(alo[mt], &Als[rr][cc]);                                  \
            }                                                                    \
            _Pragma("unroll")                                                    \
            for (int nt = 0; nt < 2; nt++) {                                     \
                const int rr = ks * 16 + (lane & 15);                            \
                const int cc = wn * 32 + nt * 16 + ((lane >> 4) << 3);           \
                uint32_t th[4], tl[4];                                           \
                ldsm_x4t(th, &Bhs[rr][cc]);                                      \
                ldsm_x4t(tl, &Bls[rr][cc]);                                      \
                bhi[nt * 2][0] = th[0]; bhi[nt * 2][1] = th[1];                  \
                bhi[nt * 2 + 1][0] = th[2]; bhi[nt * 2 + 1][1] = th[3];          \
                blo[nt * 2][0] = tl[0]; blo[nt * 2][1] = tl[1];                  \
                blo[nt * 2 + 1][0] = tl[2]; blo[nt * 2 + 1][1] = tl[3];          \
            }                                                                    \
            _Pragma("unroll")                                                    \
            for (int mt = 0; mt < 2; mt++)                                       \
                _Pragma("unroll")                                                \
                for (int nb = 0; nb < 4; nb++) {                                 \
                    mma_bf16(acc[mt][nb], ahi[mt], bhi[nb]);                     \
                    mma_bf16(acc[mt][nb], ahi[mt], blo[nb]);                     \
                    mma_bf16(acc[mt][nb], alo[mt], bhi[nb]);                     \
                }                                                                \
        }                                                                        \
        __syncthreads();                                                         \
    }

// FFN2 variant: C += r (+ out2 rows < N_NODES).   N == 128.
__global__ __launch_bounds__(256) void k_hgemm64_acc(
    const float* __restrict__ A,
    const bf16* __restrict__ Bh, const bf16* __restrict__ Bl,
    const float* __restrict__ bias, float* __restrict__ C,
    float* __restrict__ out2, int M, int K)
{
    __shared__ __align__(16) bf16 Ahs[BM64][BK + APAD];
    __shared__ __align__(16) bf16 Als[BM64][BK + APAD];
    __shared__ __align__(16) bf16 Bhs[BK][BN + BPAD];
    __shared__ __align__(16) bf16 Bls[BK][BN + BPAD];

    const int bm = blockIdx.y * BM64;
    const int tid = threadIdx.x;
    const int lane = tid & 31;
    const int w = tid >> 5;
    const int wm = w & 1;
    const int wn = w >> 1;

    const int ar0 = tid >> 3;
    const int ac  = (tid & 7) << 2;
    const int bbr = tid >> 4;
    const int bbc = (tid & 15) << 3;

    float acc[2][4][4];
    #pragma unroll
    for (int i = 0; i < 2; i++)
        #pragma unroll
        for (int j = 0; j < 4; j++)
            #pragma unroll
            for (int t = 0; t < 4; t++) acc[i][j][t] = 0.0f;

    GEMM64_MAINLOOP()

    const int g = lane >> 2;
    const int t4 = lane & 3;
    #pragma unroll
    for (int mt = 0; mt < 2; mt++) {
        #pragma unroll
        for (int nb = 0; nb < 4; nb++) {
            int col = wn * 32 + nb * 8 + t4 * 2;
            float b0 = bias[col], b1 = bias[col + 1];
            #pragma unroll
            for (int half = 0; half < 2; half++) {
                int row = bm + wm * 32 + mt * 16 + g + half * 8;
                if (row >= M) continue;
                float* cp = C + (size_t)row * 128 + col;
                float2 old = *(const float2*)cp;
                float v0 = acc[mt][nb][half * 2 + 0] + b0 + old.x;
                float v1 = acc[mt][nb][half * 2 + 1] + b1 + old.y;
                *(float2*)cp = make_float2(v0, v1);
                if (out2 && row < N_NODES)
                    *(float2*)(out2 + (size_t)row * 128 + col) = make_float2(v0, v1);
            }
        }
    }
}

// o-proj variant: xv = LN(xv + r).   N == 128.
// Block VN_BLOCK additionally finalizes the virtual-node row of agg in its
// prologue (replaces the separate k_vn_final launch).
__global__ __launch_bounds__(256) void k_hgemm64_ln(
    const float* __restrict__ A,        // agg (read by mainloop)
    float* __restrict__ aggw,           // agg (written by vn finalize)
    const float* __restrict__ vnacc2, const float* __restrict__ vnsum2,
    const bf16* __restrict__ Bh, const bf16* __restrict__ Bl,
    const float* __restrict__ bias, float* __restrict__ C,
    const float* __restrict__ lng, const float* __restrict__ lnb,
    int M, int K)
{
    __shared__ __align__(16) bf16 Ahs[BM64][BK + APAD];
    __shared__ __align__(16) bf16 Als[BM64][BK + APAD];
    __shared__ __align__(16) bf16 Bhs[BK][BN + BPAD];
    __shared__ __align__(16) bf16 Bls[BK][BN + BPAD];
    __shared__ float rsum[BM64][4], rsq[BM64][4];

    const int bm = blockIdx.y * BM64;
    const int tid = threadIdx.x;
    const int lane = tid & 31;
    const int w = tid >> 5;
    const int wm = w & 1;
    const int wn = w >> 1;

    const int ar0 = tid >> 3;
    const int ac  = (tid & 7) << 2;
    const int bbr = tid >> 4;
    const int bbc = (tid & 15) << 3;

    // vn finalize (only the block that owns row N_NODES; runs before any
    // A-tile loads of that row, then syncs)
    if (blockIdx.y == VN_BLOCK) {
        if (tid < HIDDEN) {
            int head = tid >> 4;
            float accv = 0.0f, ssum = 0.0f;
            for (int s = 0; s < VN_SLOTS; s++) {
                accv += vnacc2[(size_t)s * HIDDEN + tid];
                ssum += vnsum2[s * HEADS + head];
            }
            aggw[(size_t)N_NODES * 256 + tid] = accv / (ssum + 1e-16f);
        }
        __syncthreads();
    }

    float acc[2][4][4];
    #pragma unroll
    for (int i = 0; i < 2; i++)
        #pragma unroll
        for (int j = 0; j < 4; j++)
            #pragma unroll
            for (int t = 0; t < 4; t++) acc[i][j][t] = 0.0f;

    GEMM64_MAINLOOP()

    const int g = lane >> 2;
    const int t4 = lane & 3;

    // bias + residual
    #pragma unroll
    for (int mt = 0; mt < 2; mt++) {
        #pragma unroll
        for (int nb = 0; nb < 4; nb++) {
            int col = wn * 32 + nb * 8 + t4 * 2;
            float b0 = bias[col], b1 = bias[col + 1];
            #pragma unroll
            for (int half = 0; half < 2; half++) {
                int row = bm + wm * 32 + mt * 16 + g + half * 8;
                float v0 = acc[mt][nb][half * 2 + 0] + b0;
                float v1 = acc[mt][nb][half * 2 + 1] + b1;
                if (row < M) {
                    float2 old = *(const float2*)(C + (size_t)row * 128 + col);
                    v0 += old.x; v1 += old.y;
                }
                acc[mt][nb][half * 2 + 0] = v0;
                acc[mt][nb][half * 2 + 1] = v1;
            }
        }
    }

    // per-row partial sums across wn = 0..3
    #pragma unroll
    for (int mt = 0; mt < 2; mt++) {
        #pragma unroll
        for (int half = 0; half < 2; half++) {
            float s = 0.0f, q = 0.0f;
            #pragma unroll
            for (int nb = 0; nb < 4; nb++) {
                float v0 = acc[mt][nb][half * 2 + 0];
                float v1 = acc[mt][nb][half * 2 + 1];
                s += v0 + v1;
                q += v0 * v0 + v1 * v1;
            }
            s += __shfl_xor_sync(0xffffffffu, s, 1);
            s += __shfl_xor_sync(0xffffffffu, s, 2);
            q += __shfl_xor_sync(0xffffffffu, q, 1);
            q += __shfl_xor_sync(0xffffffffu, q, 2);
            if (t4 == 0) {
                int rl = wm * 32 + mt * 16 + g + half * 8;
                rsum[rl][wn] = s;
                rsq[rl][wn] = q;
            }
        }
    }
    __syncthreads();

    #pragma unroll
    for (int mt = 0; mt < 2; mt++) {
        #pragma unroll
        for (int nb = 0; nb < 4; nb++) {
            int col = wn * 32 + nb * 8 + t4 * 2;
            float g0 = lng[col], g1 = lng[col + 1];
            float e0 = lnb[col], e1 = lnb[col + 1];
            #pragma unroll
            for (int half = 0; half < 2; half++) {
                int rl = wm * 32 + mt * 16 + g + half * 8;
                int row = bm + rl;
                if (row >= M) continue;
                float mu  = (rsum[rl][0] + rsum[rl][1] + rsum[rl][2] + rsum[rl][3])
                            * (1.0f / HIDDEN);
                float var = (rsq[rl][0] + rsq[rl][1] + rsq[rl][2] + rsq[rl][3])
                            * (1.0f / HIDDEN) - mu * mu;
                float inv = rsqrtf(var + 1e-5f);
                float v0 = (acc[mt][nb][half * 2 + 0] - mu) * inv * g0 + e0;
                float v1 = (acc[mt][nb][half * 2 + 1] - mu) * inv * g1 + e1;
                *(float2*)(C + (size_t)row * 128 + col) = make_float2(v0, v1);
            }
        }
    }
}

// ---------------------------------------------------------------------------
// Combined gather: warps [0,N_NODES) local, rest expander.
// Launched with 128-thread blocks (4 warps) for better load balance.
// ---------------------------------------------------------------------------
__global__ void k_gather_both(const float* __restrict__ qkv, float* __restrict__ agg,
                              const int* __restrict__ rowptr,
                              const int* __restrict__ esrcL,
                              const int* __restrict__ esrcE)
{
    int wrp = (blockIdx.x * blockDim.x + threadIdx.x) >> 5;
    int lane = threadIdx.x & 31;
    const int total = N_NODES + NV;
    if (wrp >= total) return;

    const bool isExp = (wrp >= N_NODES);
    const int d = isExp ? (wrp - N_NODES) : wrp;
    const int qoff = isExp ? 384 : 0;
    const int* esrc = isExp ? esrcE : esrcL;

    float4 qd = *(const float4*)(qkv + (size_t)d * QKV6 + qoff + lane * 4);
    float4 vacc = make_float4(0.f, 0.f, 0.f, 0.f);
    float ssum = 0.0f;

    int beg, end, addVN;
    if (isExp) { beg = d * 4;      end = beg + 4;       addVN = 0; }
    else       { beg = rowptr[d];  end = rowptr[d + 1]; addVN = 1; }

    for (int e = beg; e <= end; e++) {
        int s;
        if (e < end) s = esrc[e];
        else if (addVN) s = N_NODES;
        else break;
        const float* row = qkv + (size_t)s * QKV6 + qoff;
        float4 ka = *(const float4*)(row + 128 + lane * 4);
        float dp = qd.x * ka.x + qd.y * ka.y + qd.z * ka.z + qd.w * ka.w;
        dp += __shfl_xor_sync(0xffffffffu, dp, 1);
        dp += __shfl_xor_sync(0xffffffffu, dp, 2);
        float ex = __expf(dp * 0.25f);
        float4 va = *(const float4*)(row + 256 + lane * 4);
        vacc.x = fmaf(ex, va.x, vacc.x);
        vacc.y = fmaf(ex, va.y, vacc.y);
        vacc.z = fmaf(ex, va.z, vacc.z);
        vacc.w = fmaf(ex, va.w, vacc.w);
        ssum += ex;
    }
    float inv = 1.0f / (ssum + 1e-16f);
    *(float4*)(agg + (size_t)d * 256 + (isExp ? 128 : 0) + lane * 4) =
        make_float4(vacc.x * inv, vacc.y * inv, vacc.z * inv, vacc.w * inv);
}

// ---------------------------------------------------------------------------
// Virtual node partials (separate kernel; 128-thread blocks)
// ---------------------------------------------------------------------------
__global__ void k_vn_partial(const float* __restrict__ qkv,
                             float* __restrict__ vnacc2, float* __restrict__ vnsum2)
{
    int wrp = (blockIdx.x * blockDim.x + threadIdx.x) >> 5;
    int lane = threadIdx.x & 31;

    float4 qd = *(const float4*)(qkv + (size_t)N_NODES * QKV6 + lane * 4);
    float4 vacc = make_float4(0.f, 0.f, 0.f, 0.f);
    float ssum = 0.0f;

    for (int s = wrp; s < N_NODES; s += VN_SLOTS) {
        const float* row = qkv + (size_t)s * QKV6;
        float4 ka = *(const float4*)(row + 128 + lane * 4);
        float dp = qd.x * ka.x + qd.y * ka.y + qd.z * ka.z + qd.w * ka.w;
        dp += __shfl_xor_sync(0xffffffffu, dp, 1);
        dp += __shfl_xor_sync(0xffffffffu, dp, 2);
        float ex = __expf(dp * 0.25f);
        float4 va = *(const float4*)(row + 256 + lane * 4);
        vacc.x = fmaf(ex, va.x, vacc.x);
        vacc.y = fmaf(ex, va.y, vacc.y);
        vacc.z = fmaf(ex, va.z, vacc.z);
        vacc.w = fmaf(ex, va.w, vacc.w);
        ssum += ex;
    }
    *(float4*)(vnacc2 + (size_t)wrp * HIDDEN + lane * 4) = vacc;
    if ((lane & 3) == 0) vnsum2[wrp * HEADS + (lane >> 2)] = ssum;
}

// ---------------------------------------------------------------------------
// Host-side orchestration
// ---------------------------------------------------------------------------
static inline dim3 grid1(size_t n, int bs) { return dim3((unsigned)((n + bs - 1) / bs)); }

extern "C" void kernel_launch(void* const* d_in, const int* in_sizes, int n_in,
                              void* d_out, int out_size)
{
    (void)n_in; (void)in_sizes; (void)out_size;
    const float* x         = (const float*)d_in[0];
    const int*   edge_idx  = (const int*)  d_in[1];
    const int*   exp_edges = (const int*)  d_in[2];
    const float* lq_w = (const float*)d_in[3];   const float* lq_b = (const float*)d_in[4];
    const float* lk_w = (const float*)d_in[5];   const float* lk_b = (const float*)d_in[6];
    const float* lv_w = (const float*)d_in[7];   const float* lv_b = (const float*)d_in[8];
    const float* lo_w = (const float*)d_in[9];   const float* lo_b = (const float*)d_in[10];
    const float* eq_w = (const float*)d_in[11];  const float* eq_b = (const float*)d_in[12];
    const float* ek_w = (const float*)d_in[13];  const float* ek_b = (const float*)d_in[14];
    const float* ev_w = (const float*)d_in[15];  const float* ev_b = (const float*)d_in[16];
    const float* eo_w = (const float*)d_in[17];  const float* eo_b = (const float*)d_in[18];
    const float* ln_g = (const float*)d_in[19];  const float* ln_b = (const float*)d_in[20];
    const float* ffn_w1 = (const float*)d_in[21]; const float* ffn_b1 = (const float*)d_in[22];
    const float* ffn_w2 = (const float*)d_in[23]; const float* ffn_b2 = (const float*)d_in[24];

    float *xv, *qkv, *agg, *h1, *bqkv, *bo, *vnacc2, *vnsum2;
    bf16 *wqkvh, *wqkvl, *woh, *wol, *w1h, *w1l, *w2h, *w2l;
    int *cnt, *rowptrL, *esrcL, *esrcE, *cursor, *bsum;
    cudaGetSymbolAddress((void**)&xv,      g_xv);
    cudaGetSymbolAddress((void**)&qkv,     g_qkv);
    cudaGetSymbolAddress((void**)&agg,     g_agg);
    cudaGetSymbolAddress((void**)&h1,      g_h1);
    cudaGetSymbolAddress((void**)&wqkvh,   g_wqkvh);
    cudaGetSymbolAddress((void**)&wqkvl,   g_wqkvl);
    cudaGetSymbolAddress((void**)&woh,     g_woh);
    cudaGetSymbolAddress((void**)&wol,     g_wol);
    cudaGetSymbolAddress((void**)&w1h,     g_w1h);
    cudaGetSymbolAddress((void**)&w1l,     g_w1l);
    cudaGetSymbolAddress((void**)&w2h,     g_w2h);
    cudaGetSymbolAddress((void**)&w2l,     g_w2l);
    cudaGetSymbolAddress((void**)&bqkv,    g_bqkv);
    cudaGetSymbolAddress((void**)&bo,      g_bo);
    cudaGetSymbolAddress((void**)&vnacc2,  g_vnacc2);
    cudaGetSymbolAddress((void**)&vnsum2,  g_vnsum2);
    cudaGetSymbolAddress((void**)&cnt,     g_cnt);
    cudaGetSymbolAddress((void**)&rowptrL, g_rowptrL);
    cudaGetSymbolAddress((void**)&esrcL,   g_esrcL);
    cudaGetSymbolAddress((void**)&esrcE,   g_esrcE);
    cudaGetSymbolAddress((void**)&cursor,  g_cursor);
    cudaGetSymbolAddress((void**)&bsum,    g_bsum);

    const size_t nvh = (size_t)NV * HIDDEN;

    // ---- setup ----
    k_build_xv<<<grid1(nvh / 4, 256), 256>>>((const float4*)x, (float4*)xv);
    k_zero_i<<<grid1(NV, 256), 256>>>(cnt, NV);
    k_hist<<<grid1(N_EDGES, 256), 256>>>(edge_idx + N_EDGES, N_EDGES, cnt);
    {
        int nblk = (NV + 1023) / 1024;
        k_scan1<<<nblk, 1024>>>(cnt, rowptrL, bsum, NV);
        k_scan2<<<1, 32>>>(bsum, nblk);
        k_scan3<<<grid1(NV, 256), 256>>>(rowptrL, bsum, cnt, cursor, NV);
    }
    k_scatter<<<grid1(N_EDGES, 256), 256>>>(edge_idx, edge_idx + N_EDGES, N_EDGES,
                                            cursor, esrcL);
    k_build_exp_all<<<grid1((size_t)LAYERS * E_EXP, 256), 256>>>(exp_edges, esrcE);
    k_pack_all<<<grid1((size_t)LAYERS * HIDDEN * QKV6, 256), 256>>>(
        lq_w, lk_w, lv_w, eq_w, ek_w, ev_w,
        lq_b, lk_b, lv_b, eq_b, ek_b, ev_b,
        lo_w, eo_w, lo_b, eo_b, ffn_w1, ffn_w2,
        wqkvh, wqkvl, woh, wol, w1h, w1l, w2h, w2l, bqkv, bo);

    // ---- layers ----
    for (int l = 0; l < LAYERS; l++) {
        // qkv = xv @ wqkv + b   (N=768, BM=128 kernel)
        {
            dim3 gg(QKV6 / BN, (NV + BM - 1) / BM);
            k_hgemm<<<gg, 256>>>(xv, wqkvh + (size_t)l * HIDDEN * QKV6,
                                 wqkvl + (size_t)l * HIDDEN * QKV6, bqkv + l * QKV6,
                                 qkv, NV, QKV6, HIDDEN, 0);
        }

        // combined gather (local + expander) + vn partials; 128-thread blocks
        k_gather_both<<<grid1((size_t)(N_NODES + NV) * 32, 128), 128>>>(
            qkv, agg, rowptrL, esrcL, esrcE + (size_t)l * E_EXP);
        k_vn_partial<<<VN_SLOTS * 32 / 128, 128>>>(qkv, vnacc2, vnsum2);

        // fused o-projection + residual + LN (vn-final folded into VN_BLOCK)
        {
            dim3 gg(1, (NV + BM64 - 1) / BM64);
            k_hgemm64_ln<<<gg, 256>>>(agg, agg, vnacc2, vnsum2,
                                      woh + (size_t)l * 256 * HIDDEN,
                                      wol + (size_t)l * 256 * HIDDEN, bo + l * HIDDEN,
                                      xv, ln_g + (size_t)l * HIDDEN,
                                      ln_b + (size_t)l * HIDDEN, NV, 256);
        }

        // FFN1: h1 = gelu(xv@w1+b1)   (N=512, BM=128 kernel)
        {
            dim3 gg(512 / BN, (NV + BM - 1) / BM);
            k_hgemm<<<gg, 256>>>(xv, w1h + (size_t)l * HIDDEN * 512,
                                 w1l + (size_t)l * HIDDEN * 512, ffn_b1 + (size_t)l * 512,
                                 h1, NV, 512, HIDDEN, 2);
        }
        // FFN2: xv += h1@w2+b2 (BM=64; last layer also writes d_out)
        {
            dim3 gg(1, (NV + BM64 - 1) / BM64);
            k_hgemm64_acc<<<gg, 256>>>(h1, w2h + (size_t)l * 512 * HIDDEN,
                                       w2l + (size_t)l * 512 * HIDDEN,
                                       ffn_b2 + (size_t)l * HIDDEN, xv,
                                       (l == LAYERS - 1) ? (float*)d_out : nullptr,
                                       NV, 512);
        }
    }
}

// round 17
// speedup vs baseline: 1.0955x; 1.0130x over previous
#include <cuda_runtime.h>
#include <cuda_bf16.h>
#include <math.h>
#include <stdint.h>

// ---------------------------------------------------------------------------
// Problem constants
// ---------------------------------------------------------------------------
#define N_NODES 20000
#define N_EDGES 320000
#define HIDDEN  128
#define HEADS   8
#define LAYERS  3
#define NV      (N_NODES + 1)
#define E_EXP   (NV * 4)                 // 80004 per layer
#define QKV6    (6 * HIDDEN)             // 768: lq|lk|lv|eq|ek|ev

typedef __nv_bfloat16  bf16;
typedef __nv_bfloat162 bf162;

// ---------------------------------------------------------------------------
// Scratch (device globals; no allocations)
// ---------------------------------------------------------------------------
__device__ float g_xv   [(size_t)NV * HIDDEN];
__device__ float g_qkv  [(size_t)NV * QKV6];
__device__ float g_agg  [(size_t)NV * 256];           // [local 128 | exp 128]
__device__ float g_h1   [(size_t)NV * 4 * HIDDEN];
// packed + PRE-SPLIT weights (B operands only)
__device__ bf16  g_wqkvh[(size_t)LAYERS * HIDDEN * QKV6];
__device__ bf16  g_wqkvl[(size_t)LAYERS * HIDDEN * QKV6];
__device__ bf16  g_woh  [(size_t)LAYERS * 256 * HIDDEN];
__device__ bf16  g_wol  [(size_t)LAYERS * 256 * HIDDEN];
__device__ bf16  g_w1h  [(size_t)LAYERS * HIDDEN * 512];
__device__ bf16  g_w1l  [(size_t)LAYERS * HIDDEN * 512];
__device__ bf16  g_w2h  [(size_t)LAYERS * 512 * HIDDEN];
__device__ bf16  g_w2l  [(size_t)LAYERS * 512 * HIDDEN];
__device__ float g_bqkv [LAYERS * QKV6];
__device__ float g_bo   [LAYERS * HIDDEN];
// CSR scratch
__device__ int   g_cnt    [NV];
__device__ int   g_rowptrL[NV + 1];
__device__ int   g_esrcL  [N_EDGES];
__device__ int   g_esrcE  [LAYERS * E_EXP];
__device__ int   g_cursor [NV];
__device__ int   g_bsum   [32];
// virtual-node reduction scratch
#define VN_SLOTS 512
__device__ float g_vnacc2[VN_SLOTS * HIDDEN];
__device__ float g_vnsum2[VN_SLOTS * HEADS];

// ---------------------------------------------------------------------------
// Helpers
// ---------------------------------------------------------------------------
__device__ __forceinline__ void split2(float x, bf16& h, bf16& l) {
    h = __float2bfloat16_rn(x);
    l = __float2bfloat16_rn(x - __bfloat162float(h));
}

// ---------------------------------------------------------------------------
// Merged setup kernel: build_xv + pack/pre-split all weights + expander CSR.
// All three tasks are independent; disjoint index-range branches.
// Grid covers max range = NV*HIDDEN/4 = 640,032.
// ---------------------------------------------------------------------------
__global__ void k_setup_all(
    const float4* __restrict__ x, float4* __restrict__ xv,
    const int* __restrict__ ee, int* __restrict__ esrcE,
    const float* __restrict__ lq_w, const float* __restrict__ lk_w,
    const float* __restrict__ lv_w, const float* __restrict__ eq_w,
    const float* __restrict__ ek_w, const float* __restrict__ ev_w,
    const float* __restrict__ lq_b, const float* __restrict__ lk_b,
    const float* __restrict__ lv_b, const float* __restrict__ eq_b,
    const float* __restrict__ ek_b, const float* __restrict__ ev_b,
    const float* __restrict__ lo_w, const float* __restrict__ eo_w,
    const float* __restrict__ lo_b, const float* __restrict__ eo_b,
    const float* __restrict__ w1, const float* __restrict__ w2,
    bf16* __restrict__ wqkvh, bf16* __restrict__ wqkvl,
    bf16* __restrict__ woh,  bf16* __restrict__ wol,
    bf16* __restrict__ w1h,  bf16* __restrict__ w1l,
    bf16* __restrict__ w2h,  bf16* __restrict__ w2l,
    float* __restrict__ bqkv, float* __restrict__ bo)
{
    int i = blockIdx.x * blockDim.x + threadIdx.x;

    // --- build xv = [x; 0] ---
    {
        const int tot = NV * HIDDEN / 4;
        const int lim = N_NODES * HIDDEN / 4;
        if (i < tot)
            xv[i] = (i < lim) ? x[i] : make_float4(0.f, 0.f, 0.f, 0.f);
    }
    // --- expander CSR for all layers (deterministic slot) ---
    if (i < LAYERS * E_EXP) {
        int l = i / E_EXP, r = i % E_EXP;
        int g = r / NV;
        int src = ee[(size_t)l * 2 * E_EXP + r];
        int dst = ee[(size_t)l * 2 * E_EXP + E_EXP + r];
        esrcE[(size_t)l * E_EXP + dst * 4 + g] = src;
    }
    // --- weight packing + pre-split ---
    const int NQ = LAYERS * HIDDEN * QKV6;
    const int NO = LAYERS * 256 * HIDDEN;
    const int NW = LAYERS * HIDDEN * 512;
    if (i < NQ) {
        int l = i / (HIDDEN * QKV6);
        int r = i % (HIDDEN * QKV6);
        int k = r / QKV6, n = r % QKV6;
        int sel = n >> 7, c = n & 127;
        const float* w[6] = {lq_w, lk_w, lv_w, eq_w, ek_w, ev_w};
        float v = w[sel][(size_t)l * HIDDEN * HIDDEN + k * HIDDEN + c];
        split2(v, wqkvh[i], wqkvl[i]);
    }
    if (i < NO) {
        int l = i / (256 * HIDDEN);
        int r = i % (256 * HIDDEN);
        int k = r / HIDDEN, n = r % HIDDEN;
        float v = (k < 128)
            ? lo_w[(size_t)l * HIDDEN * HIDDEN + k * HIDDEN + n]
            : eo_w[(size_t)l * HIDDEN * HIDDEN + (k - 128) * HIDDEN + n];
        split2(v, woh[i], wol[i]);
    }
    if (i < NW) {
        split2(w1[i], w1h[i], w1l[i]);
        split2(w2[i], w2h[i], w2l[i]);
    }
    if (i < LAYERS * QKV6) {
        int l = i / QKV6, n = i % QKV6;
        int sel = n >> 7, c = n & 127;
        const float* b[6] = {lq_b, lk_b, lv_b, eq_b, ek_b, ev_b};
        bqkv[i] = b[sel][l * HIDDEN + c];
    }
    if (i < LAYERS * HIDDEN) {
        int l = i / HIDDEN, n = i % HIDDEN;
        bo[i] = lo_b[l * HIDDEN + n] + eo_b[l * HIDDEN + n];
    }
}

// ---------------------------------------------------------------------------
// Local CSR build: zero -> hist -> scan1 -> scan3 (with inline bsum scan) -> scatter
// ---------------------------------------------------------------------------
__global__ void k_zero_i(int* p, int n) {
    int i = blockIdx.x * blockDim.x + threadIdx.x;
    if (i < n) p[i] = 0;
}
__global__ void k_hist(const int* __restrict__ dst, int E, int* __restrict__ cnt) {
    int e = blockIdx.x * blockDim.x + threadIdx.x;
    if (e < E) atomicAdd(&cnt[dst[e]], 1);
}
__global__ void k_scan1(const int* __restrict__ cnt, int* __restrict__ rowptr,
                        int* __restrict__ bsum, int n) {
    __shared__ int wsum[32];
    const int tid = threadIdx.x, lane = tid & 31, wid = tid >> 5;
    int i = blockIdx.x * 1024 + tid;
    int x = (i < n) ? cnt[i] : 0;
    #pragma unroll
    for (int off = 1; off < 32; off <<= 1) {
        int t = __shfl_up_sync(0xffffffffu, x, off);
        if (lane >= off) x += t;
    }
    if (lane == 31) wsum[wid] = x;
    __syncthreads();
    if (wid == 0) {
        int y = wsum[lane];
        #pragma unroll
        for (int off = 1; off < 32; off <<= 1) {
            int t = __shfl_up_sync(0xffffffffu, y, off);
            if (lane >= off) y += t;
        }
        wsum[lane] = y;
    }
    __syncthreads();
    int total = x + ((wid > 0) ? wsum[wid - 1] : 0);
    if (i < n) rowptr[i + 1] = total;
    if (tid == 1023) bsum[blockIdx.x] = total;
}
// scan3 with scan2 folded in: each block redundantly computes the exclusive
// prefix of the (<=32) block sums in its first warp.
__global__ void k_scan3(int* __restrict__ rowptr, const int* __restrict__ bsum,
                        const int* __restrict__ cnt, int* __restrict__ cursor,
                        int n, int nb) {
    __shared__ int pref[32];
    if (threadIdx.x < 32) {
        int lane = threadIdx.x;
        int v = (lane < nb) ? bsum[lane] : 0;
        int orig = v;
        #pragma unroll
        for (int off = 1; off < 32; off <<= 1) {
            int t = __shfl_up_sync(0xffffffffu, v, off);
            if (lane >= off) v += t;
        }
        pref[lane] = v - orig;   // exclusive prefix
    }
    __syncthreads();
    int i = blockIdx.x * blockDim.x + threadIdx.x;
    if (i < n) {
        int v = rowptr[i + 1] + pref[i >> 10];
        rowptr[i + 1] = v;
        cursor[i] = v - cnt[i];
        if (i == 0) rowptr[0] = 0;
    }
}
__global__ void k_scatter(const int* __restrict__ src, const int* __restrict__ dst,
                          int E, int* __restrict__ cursor, int* __restrict__ esrc) {
    int e = blockIdx.x * blockDim.x + threadIdx.x;
    if (e < E) {
        int pos = atomicAdd(&cursor[dst[e]], 1);
        esrc[pos] = src[e];
    }
}

// ---------------------------------------------------------------------------
// Common GEMM pieces
// ---------------------------------------------------------------------------
#define BM 128
#define BN 128
#define BK 32
#define APAD 8
#define BPAD 8

__device__ __forceinline__ void ldsm_x4(uint32_t* r, const void* p) {
    uint32_t a = (uint32_t)__cvta_generic_to_shared(p);
    asm volatile("ldmatrix.sync.aligned.m8n8.x4.shared.b16 {%0,%1,%2,%3}, [%4];"
                 : "=r"(r[0]), "=r"(r[1]), "=r"(r[2]), "=r"(r[3]) : "r"(a));
}
__device__ __forceinline__ void ldsm_x4t(uint32_t* r, const void* p) {
    uint32_t a = (uint32_t)__cvta_generic_to_shared(p);
    asm volatile("ldmatrix.sync.aligned.m8n8.x4.trans.shared.b16 {%0,%1,%2,%3}, [%4];"
                 : "=r"(r[0]), "=r"(r[1]), "=r"(r[2]), "=r"(r[3]) : "r"(a));
}
__device__ __forceinline__ void mma_bf16(float* c, const uint32_t* a, const uint32_t* b) {
    asm volatile("mma.sync.aligned.m16n8k16.row.col.f32.bf16.bf16.f32 "
                 "{%0,%1,%2,%3}, {%4,%5,%6,%7}, {%8,%9}, {%0,%1,%2,%3};"
                 : "+f"(c[0]), "+f"(c[1]), "+f"(c[2]), "+f"(c[3])
                 : "r"(a[0]), "r"(a[1]), "r"(a[2]), "r"(a[3]), "r"(b[0]), "r"(b[1]));
}

// ---------------------------------------------------------------------------
// BM=128 GEMM: used for N=768 (qkv) and N=512 (FFN1)
//   mode 0: C = r;  2: C = gelu(r)
// ---------------------------------------------------------------------------
__global__ __launch_bounds__(256) void k_hgemm(
    const float* __restrict__ A,
    const bf16* __restrict__ Bh, const bf16* __restrict__ Bl,
    const float* __restrict__ bias, float* __restrict__ C,
    int M, int N, int K, int mode)
{
    __shared__ __align__(16) bf16 Ahs[BM][BK + APAD];
    __shared__ __align__(16) bf16 Als[BM][BK + APAD];
    __shared__ __align__(16) bf16 Bhs[BK][BN + BPAD];
    __shared__ __align__(16) bf16 Bls[BK][BN + BPAD];

    const int bm = blockIdx.y * BM;
    const int bn = blockIdx.x * BN;
    const int tid = threadIdx.x;
    const int lane = tid & 31;
    const int w = tid >> 5;
    const int wm = w & 3;
    const int wn = w >> 2;

    const int ar0 = tid >> 3;
    const int ac  = (tid & 7) << 2;
    const int bbr = tid >> 4;
    const int bbc = (tid & 15) << 3;

    float acc[2][8][4];
    #pragma unroll
    for (int i = 0; i < 2; i++)
        #pragma unroll
        for (int j = 0; j < 8; j++)
            #pragma unroll
            for (int t = 0; t < 4; t++) acc[i][j][t] = 0.0f;

    for (int k0 = 0; k0 < K; k0 += BK) {
        #pragma unroll
        for (int p = 0; p < 4; p++) {
            int r = ar0 + p * 32;
            float4 v = make_float4(0.f, 0.f, 0.f, 0.f);
            if (bm + r < M) v = *(const float4*)(A + (size_t)(bm + r) * K + k0 + ac);
            bf16 h, l;
            split2(v.x, h, l); Ahs[r][ac + 0] = h; Als[r][ac + 0] = l;
            split2(v.y, h, l); Ahs[r][ac + 1] = h; Als[r][ac + 1] = l;
            split2(v.z, h, l); Ahs[r][ac + 2] = h; Als[r][ac + 2] = l;
            split2(v.w, h, l); Ahs[r][ac + 3] = h; Als[r][ac + 3] = l;
        }
        #pragma unroll
        for (int p = 0; p < 2; p++) {
            int r = bbr + p * 16;
            uint4 vh = *(const uint4*)(Bh + (size_t)(k0 + r) * N + bn + bbc);
            uint4 vl = *(const uint4*)(Bl + (size_t)(k0 + r) * N + bn + bbc);
            *(uint4*)&Bhs[r][bbc] = vh;
            *(uint4*)&Bls[r][bbc] = vl;
        }
        __syncthreads();

        #pragma unroll
        for (int ks = 0; ks < 2; ks++) {
            uint32_t ahi[2][4], alo[2][4], bhi[8][2], blo[8][2];
            #pragma unroll
            for (int mt = 0; mt < 2; mt++) {
                const int rr = wm * 32 + mt * 16 + (lane & 15);
                const int cc = ks * 16 + ((lane >> 4) << 3);
                ldsm_x4(ahi[mt], &Ahs[rr][cc]);
                ldsm_x4(alo[mt], &Als[rr][cc]);
            }
            #pragma unroll
            for (int nt = 0; nt < 4; nt++) {
                const int rr = ks * 16 + (lane & 15);
                const int cc = wn * 64 + nt * 16 + ((lane >> 4) << 3);
                uint32_t th[4], tl[4];
                ldsm_x4t(th, &Bhs[rr][cc]);
                ldsm_x4t(tl, &Bls[rr][cc]);
                bhi[nt * 2][0] = th[0]; bhi[nt * 2][1] = th[1];
                bhi[nt * 2 + 1][0] = th[2]; bhi[nt * 2 + 1][1] = th[3];
                blo[nt * 2][0] = tl[0]; blo[nt * 2][1] = tl[1];
                blo[nt * 2 + 1][0] = tl[2]; blo[nt * 2 + 1][1] = tl[3];
            }
            #pragma unroll
            for (int mt = 0; mt < 2; mt++)
                #pragma unroll
                for (int nb = 0; nb < 8; nb++) {
                    mma_bf16(acc[mt][nb], ahi[mt], bhi[nb]);
                    mma_bf16(acc[mt][nb], ahi[mt], blo[nb]);
                    mma_bf16(acc[mt][nb], alo[mt], bhi[nb]);
                }
        }
        __syncthreads();
    }

    const int g = lane >> 2;
    const int t4 = lane & 3;
    #pragma unroll
    for (int mt = 0; mt < 2; mt++) {
        #pragma unroll
        for (int nb = 0; nb < 8; nb++) {
            int col = bn + wn * 64 + nb * 8 + t4 * 2;
            float b0 = bias[col], b1 = bias[col + 1];
            #pragma unroll
            for (int half = 0; half < 2; half++) {
                int row = bm + wm * 32 + mt * 16 + g + half * 8;
                if (row >= M) continue;
                float v0 = acc[mt][nb][half * 2 + 0] + b0;
                float v1 = acc[mt][nb][half * 2 + 1] + b1;
                if (mode == 2) {
                    v0 = 0.5f * v0 * (1.0f + erff(v0 * 0.70710678118654752440f));
                    v1 = 0.5f * v1 * (1.0f + erff(v1 * 0.70710678118654752440f));
                }
                *(float2*)(C + (size_t)row * N + col) = make_float2(v0, v1);
            }
        }
    }
}

// ---------------------------------------------------------------------------
// BM=64 x BN=128 GEMM variants for N==128 (o-proj LN, FFN2)
// ---------------------------------------------------------------------------
#define BM64 64
#define VN_BLOCK (N_NODES / BM64)   // block y index owning row N_NODES (312)

#define GEMM64_MAINLOOP()                                                        \
    for (int k0 = 0; k0 < K; k0 += BK) {                                         \
        _Pragma("unroll")                                                        \
        for (int p = 0; p < 2; p++) {                                            \
            int r = ar0 + p * 32;                                                \
            float4 v = make_float4(0.f, 0.f, 0.f, 0.f);                          \
            if (bm + r < M) v = *(const float4*)(A + (size_t)(bm + r) * K + k0 + ac); \
            bf16 h, l;                                                           \
            split2(v.x, h, l); Ahs[r][ac + 0] = h; Als[r][ac + 0] = l;           \
            split2(v.y, h, l); Ahs[r][ac + 1] = h; Als[r][ac + 1] = l;           \
            split2(v.z, h, l); Ahs[r][ac + 2] = h; Als[r][ac + 2] = l;           \
            split2(v.w, h, l); Ahs[r][ac + 3] = h; Als[r][ac + 3] = l;           \
        }                                                                        \
        _Pragma("unroll")                                                        \
        for (int p = 0; p < 2; p++) {                                            \
            int r = bbr + p * 16;                                                \
            uint4 vh = *(const uint4*)(Bh + (size_t)(k0 + r) * 128 + bbc);       \
            uint4 vl = *(const uint4*)(Bl + (size_t)(k0 + r) * 128 + bbc);       \
            *(uint4*)&Bhs[r][bbc] = vh;                                          \
            *(uint4*)&Bls[r][bbc] = vl;                                          \
        }                                                                        \
        __syncthreads();                                                         \
        _Pragma("unroll")                                                        \
        for (int ks = 0; ks < 2; ks++) {                                         \
            uint32_t ahi[2][4], alo[2][4], bhi[4][2], blo[4][2];                 \
            _Pragma("unroll")                                                    \
            for (int mt = 0; mt < 2; mt++) {                                     \
                const int rr = wm * 32 + mt * 16 + (lane & 15);                  \
                const int cc = ks * 16 + ((lane >> 4) << 3);                     \
                ldsm_x4(ahi[mt], &Ahs[rr][cc]);                                  \
                ldsm_x4(alo[mt], &Als[rr][cc]);                                  \
            }                                                                    \
            _Pragma("unroll")                                                    \
            for (int nt = 0; nt < 2; nt++) {                                     \
                const int rr = ks * 16 + (lane & 15);                            \
                const int cc = wn * 32 + nt * 16 + ((lane >> 4) << 3);           \
                uint32_t th[4], tl[4];                                           \
                ldsm_x4t(th, &Bhs[rr][cc]);                                      \
                ldsm_x4t(tl, &Bls[rr][cc]);                                      \
                bhi[nt * 2][0] = th[0]; bhi[nt * 2][1] = th[1];                  \
                bhi[nt * 2 + 1][0] = th[2]; bhi[nt * 2 + 1][1] = th[3];          \
                blo[nt * 2][0] = tl[0]; blo[nt * 2][1] = tl[1];                  \
                blo[nt * 2 + 1][0] = tl[2]; blo[nt * 2 + 1][1] = tl[3];          \
            }                                                                    \
            _Pragma("unroll")                                                    \
            for (int mt = 0; mt < 2; mt++)                                       \
                _Pragma("unroll")                                                \
                for (int nb = 0; nb < 4; nb++) {                                 \
                    mma_bf16(acc[mt][nb], ahi[mt], bhi[nb]);                     \
                    mma_bf16(acc[mt][nb], ahi[mt], blo[nb]);                     \
                    mma_bf16(acc[mt][nb], alo[mt], bhi[nb]);                     \
                }                                                                \
        }                                                                        \
        __syncthreads();                                                         \
    }

// FFN2 variant: C += r (+ out2 rows < N_NODES).   N == 128.
__global__ __launch_bounds__(256) void k_hgemm64_acc(
    const float* __restrict__ A,
    const bf16* __restrict__ Bh, const bf16* __restrict__ Bl,
    const float* __restrict__ bias, float* __restrict__ C,
    float* __restrict__ out2, int M, int K)
{
    __shared__ __align__(16) bf16 Ahs[BM64][BK + APAD];
    __shared__ __align__(16) bf16 Als[BM64][BK + APAD];
    __shared__ __align__(16) bf16 Bhs[BK][BN + BPAD];
    __shared__ __align__(16) bf16 Bls[BK][BN + BPAD];

    const int bm = blockIdx.y * BM64;
    const int tid = threadIdx.x;
    const int lane = tid & 31;
    const int w = tid >> 5;
    const int wm = w & 1;
    const int wn = w >> 1;

    const int ar0 = tid >> 3;
    const int ac  = (tid & 7) << 2;
    const int bbr = tid >> 4;
    const int bbc = (tid & 15) << 3;

    float acc[2][4][4];
    #pragma unroll
    for (int i = 0; i < 2; i++)
        #pragma unroll
        for (int j = 0; j < 4; j++)
            #pragma unroll
            for (int t = 0; t < 4; t++) acc[i][j][t] = 0.0f;

    GEMM64_MAINLOOP()

    const int g = lane >> 2;
    const int t4 = lane & 3;
    #pragma unroll
    for (int mt = 0; mt < 2; mt++) {
        #pragma unroll
        for (int nb = 0; nb < 4; nb++) {
            int col = wn * 32 + nb * 8 + t4 * 2;
            float b0 = bias[col], b1 = bias[col + 1];
            #pragma unroll
            for (int half = 0; half < 2; half++) {
                int row = bm + wm * 32 + mt * 16 + g + half * 8;
                if (row >= M) continue;
                float* cp = C + (size_t)row * 128 + col;
                float2 old = *(const float2*)cp;
                float v0 = acc[mt][nb][half * 2 + 0] + b0 + old.x;
                float v1 = acc[mt][nb][half * 2 + 1] + b1 + old.y;
                *(float2*)cp = make_float2(v0, v1);
                if (out2 && row < N_NODES)
                    *(float2*)(out2 + (size_t)row * 128 + col) = make_float2(v0, v1);
            }
        }
    }
}

// o-proj variant: xv = LN(xv + r).   N == 128.
// Block VN_BLOCK additionally finalizes the virtual-node row of agg.
__global__ __launch_bounds__(256) void k_hgemm64_ln(
    const float* __restrict__ A,
    float* __restrict__ aggw,
    const float* __restrict__ vnacc2, const float* __restrict__ vnsum2,
    const bf16* __restrict__ Bh, const bf16* __restrict__ Bl,
    const float* __restrict__ bias, float* __restrict__ C,
    const float* __restrict__ lng, const float* __restrict__ lnb,
    int M, int K)
{
    __shared__ __align__(16) bf16 Ahs[BM64][BK + APAD];
    __shared__ __align__(16) bf16 Als[BM64][BK + APAD];
    __shared__ __align__(16) bf16 Bhs[BK][BN + BPAD];
    __shared__ __align__(16) bf16 Bls[BK][BN + BPAD];
    __shared__ float rsum[BM64][4], rsq[BM64][4];

    const int bm = blockIdx.y * BM64;
    const int tid = threadIdx.x;
    const int lane = tid & 31;
    const int w = tid >> 5;
    const int wm = w & 1;
    const int wn = w >> 1;

    const int ar0 = tid >> 3;
    const int ac  = (tid & 7) << 2;
    const int bbr = tid >> 4;
    const int bbc = (tid & 15) << 3;

    if (blockIdx.y == VN_BLOCK) {
        if (tid < HIDDEN) {
            int head = tid >> 4;
            float accv = 0.0f, ssum = 0.0f;
            for (int s = 0; s < VN_SLOTS; s++) {
                accv += vnacc2[(size_t)s * HIDDEN + tid];
                ssum += vnsum2[s * HEADS + head];
            }
            aggw[(size_t)N_NODES * 256 + tid] = accv / (ssum + 1e-16f);
        }
        __syncthreads();
    }

    float acc[2][4][4];
    #pragma unroll
    for (int i = 0; i < 2; i++)
        #pragma unroll
        for (int j = 0; j < 4; j++)
            #pragma unroll
            for (int t = 0; t < 4; t++) acc[i][j][t] = 0.0f;

    GEMM64_MAINLOOP()

    const int g = lane >> 2;
    const int t4 = lane & 3;

    // bias + residual
    #pragma unroll
    for (int mt = 0; mt < 2; mt++) {
        #pragma unroll
        for (int nb = 0; nb < 4; nb++) {
            int col = wn * 32 + nb * 8 + t4 * 2;
            float b0 = bias[col], b1 = bias[col + 1];
            #pragma unroll
            for (int half = 0; half < 2; half++) {
                int row = bm + wm * 32 + mt * 16 + g + half * 8;
                float v0 = acc[mt][nb][half * 2 + 0] + b0;
                float v1 = acc[mt][nb][half * 2 + 1] + b1;
                if (row < M) {
                    float2 old = *(const float2*)(C + (size_t)row * 128 + col);
                    v0 += old.x; v1 += old.y;
                }
                acc[mt][nb][half * 2 + 0] = v0;
                acc[mt][nb][half * 2 + 1] = v1;
            }
        }
    }

    // per-row partial sums across wn = 0..3
    #pragma unroll
    for (int mt = 0; mt < 2; mt++) {
        #pragma unroll
        for (int half = 0; half < 2; half++) {
            float s = 0.0f, q = 0.0f;
            #pragma unroll
            for (int nb = 0; nb < 4; nb++) {
                float v0 = acc[mt][nb][half * 2 + 0];
                float v1 = acc[mt][nb][half * 2 + 1];
                s += v0 + v1;
                q += v0 * v0 + v1 * v1;
            }
            s += __shfl_xor_sync(0xffffffffu, s, 1);
            s += __shfl_xor_sync(0xffffffffu, s, 2);
            q += __shfl_xor_sync(0xffffffffu, q, 1);
            q += __shfl_xor_sync(0xffffffffu, q, 2);
            if (t4 == 0) {
                int rl = wm * 32 + mt * 16 + g + half * 8;
                rsum[rl][wn] = s;
                rsq[rl][wn] = q;
            }
        }
    }
    __syncthreads();

    #pragma unroll
    for (int mt = 0; mt < 2; mt++) {
        #pragma unroll
        for (int nb = 0; nb < 4; nb++) {
            int col = wn * 32 + nb * 8 + t4 * 2;
            float g0 = lng[col], g1 = lng[col + 1];
            float e0 = lnb[col], e1 = lnb[col + 1];
            #pragma unroll
            for (int half = 0; half < 2; half++) {
                int rl = wm * 32 + mt * 16 + g + half * 8;
                int row = bm + rl;
                if (row >= M) continue;
                float mu  = (rsum[rl][0] + rsum[rl][1] + rsum[rl][2] + rsum[rl][3])
                            * (1.0f / HIDDEN);
                float var = (rsq[rl][0] + rsq[rl][1] + rsq[rl][2] + rsq[rl][3])
                            * (1.0f / HIDDEN) - mu * mu;
                float inv = rsqrtf(var + 1e-5f);
                float v0 = (acc[mt][nb][half * 2 + 0] - mu) * inv * g0 + e0;
                float v1 = (acc[mt][nb][half * 2 + 1] - mu) * inv * g1 + e1;
                *(float2*)(C + (size_t)row * 128 + col) = make_float2(v0, v1);
            }
        }
    }
}

// ---------------------------------------------------------------------------
// Combined gather: warps [0,N_NODES) local, rest expander.
// Launched with 64-thread blocks (2 warps) for better load balance.
// ---------------------------------------------------------------------------
__global__ void k_gather_both(const float* __restrict__ qkv, float* __restrict__ agg,
                              const int* __restrict__ rowptr,
                              const int* __restrict__ esrcL,
                              const int* __restrict__ esrcE)
{
    int wrp = (blockIdx.x * blockDim.x + threadIdx.x) >> 5;
    int lane = threadIdx.x & 31;
    const int total = N_NODES + NV;
    if (wrp >= total) return;

    const bool isExp = (wrp >= N_NODES);
    const int d = isExp ? (wrp - N_NODES) : wrp;
    const int qoff = isExp ? 384 : 0;
    const int* esrc = isExp ? esrcE : esrcL;

    float4 qd = *(const float4*)(qkv + (size_t)d * QKV6 + qoff + lane * 4);
    float4 vacc = make_float4(0.f, 0.f, 0.f, 0.f);
    float ssum = 0.0f;

    int beg, end, addVN;
    if (isExp) { beg = d * 4;      end = beg + 4;       addVN = 0; }
    else       { beg = rowptr[d];  end = rowptr[d + 1]; addVN = 1; }

    for (int e = beg; e <= end; e++) {
        int s;
        if (e < end) s = esrc[e];
        else if (addVN) s = N_NODES;
        else break;
        const float* row = qkv + (size_t)s * QKV6 + qoff;
        float4 ka = *(const float4*)(row + 128 + lane * 4);
        float dp = qd.x * ka.x + qd.y * ka.y + qd.z * ka.z + qd.w * ka.w;
        dp += __shfl_xor_sync(0xffffffffu, dp, 1);
        dp += __shfl_xor_sync(0xffffffffu, dp, 2);
        float ex = __expf(dp * 0.25f);
        float4 va = *(const float4*)(row + 256 + lane * 4);
        vacc.x = fmaf(ex, va.x, vacc.x);
        vacc.y = fmaf(ex, va.y, vacc.y);
        vacc.z = fmaf(ex, va.z, vacc.z);
        vacc.w = fmaf(ex, va.w, vacc.w);
        ssum += ex;
    }
    float inv = 1.0f / (ssum + 1e-16f);
    *(float4*)(agg + (size_t)d * 256 + (isExp ? 128 : 0) + lane * 4) =
        make_float4(vacc.x * inv, vacc.y * inv, vacc.z * inv, vacc.w * inv);
}

// ---------------------------------------------------------------------------
// Virtual node partials (separate kernel; 64-thread blocks)
// ---------------------------------------------------------------------------
__global__ void k_vn_partial(const float* __restrict__ qkv,
                             float* __restrict__ vnacc2, float* __restrict__ vnsum2)
{
    int wrp = (blockIdx.x * blockDim.x + threadIdx.x) >> 5;
    int lane = threadIdx.x & 31;

    float4 qd = *(const float4*)(qkv + (size_t)N_NODES * QKV6 + lane * 4);
    float4 vacc = make_float4(0.f, 0.f, 0.f, 0.f);
    float ssum = 0.0f;

    for (int s = wrp; s < N_NODES; s += VN_SLOTS) {
        const float* row = qkv + (size_t)s * QKV6;
        float4 ka = *(const float4*)(row + 128 + lane * 4);
        float dp = qd.x * ka.x + qd.y * ka.y + qd.z * ka.z + qd.w * ka.w;
        dp += __shfl_xor_sync(0xffffffffu, dp, 1);
        dp += __shfl_xor_sync(0xffffffffu, dp, 2);
        float ex = __expf(dp * 0.25f);
        float4 va = *(const float4*)(row + 256 + lane * 4);
        vacc.x = fmaf(ex, va.x, vacc.x);
        vacc.y = fmaf(ex, va.y, vacc.y);
        vacc.z = fmaf(ex, va.z, vacc.z);
        vacc.w = fmaf(ex, va.w, vacc.w);
        ssum += ex;
    }
    *(float4*)(vnacc2 + (size_t)wrp * HIDDEN + lane * 4) = vacc;
    if ((lane & 3) == 0) vnsum2[wrp * HEADS + (lane >> 2)] = ssum;
}

// ---------------------------------------------------------------------------
// Host-side orchestration
// ---------------------------------------------------------------------------
static inline dim3 grid1(size_t n, int bs) { return dim3((unsigned)((n + bs - 1) / bs)); }

extern "C" void kernel_launch(void* const* d_in, const int* in_sizes, int n_in,
                              void* d_out, int out_size)
{
    (void)n_in; (void)in_sizes; (void)out_size;
    const float* x         = (const float*)d_in[0];
    const int*   edge_idx  = (const int*)  d_in[1];
    const int*   exp_edges = (const int*)  d_in[2];
    const float* lq_w = (const float*)d_in[3];   const float* lq_b = (const float*)d_in[4];
    const float* lk_w = (const float*)d_in[5];   const float* lk_b = (const float*)d_in[6];
    const float* lv_w = (const float*)d_in[7];   const float* lv_b = (const float*)d_in[8];
    const float* lo_w = (const float*)d_in[9];   const float* lo_b = (const float*)d_in[10];
    const float* eq_w = (const float*)d_in[11];  const float* eq_b = (const float*)d_in[12];
    const float* ek_w = (const float*)d_in[13];  const float* ek_b = (const float*)d_in[14];
    const float* ev_w = (const float*)d_in[15];  const float* ev_b = (const float*)d_in[16];
    const float* eo_w = (const float*)d_in[17];  const float* eo_b = (const float*)d_in[18];
    const float* ln_g = (const float*)d_in[19];  const float* ln_b = (const float*)d_in[20];
    const float* ffn_w1 = (const float*)d_in[21]; const float* ffn_b1 = (const float*)d_in[22];
    const float* ffn_w2 = (const float*)d_in[23]; const float* ffn_b2 = (const float*)d_in[24];

    float *xv, *qkv, *agg, *h1, *bqkv, *bo, *vnacc2, *vnsum2;
    bf16 *wqkvh, *wqkvl, *woh, *wol, *w1h, *w1l, *w2h, *w2l;
    int *cnt, *rowptrL, *esrcL, *esrcE, *cursor, *bsum;
    cudaGetSymbolAddress((void**)&xv,      g_xv);
    cudaGetSymbolAddress((void**)&qkv,     g_qkv);
    cudaGetSymbolAddress((void**)&agg,     g_agg);
    cudaGetSymbolAddress((void**)&h1,      g_h1);
    cudaGetSymbolAddress((void**)&wqkvh,   g_wqkvh);
    cudaGetSymbolAddress((void**)&wqkvl,   g_wqkvl);
    cudaGetSymbolAddress((void**)&woh,     g_woh);
    cudaGetSymbolAddress((void**)&wol,     g_wol);
    cudaGetSymbolAddress((void**)&w1h,     g_w1h);
    cudaGetSymbolAddress((void**)&w1l,     g_w1l);
    cudaGetSymbolAddress((void**)&w2h,     g_w2h);
    cudaGetSymbolAddress((void**)&w2l,     g_w2l);
    cudaGetSymbolAddress((void**)&bqkv,    g_bqkv);
    cudaGetSymbolAddress((void**)&bo,      g_bo);
    cudaGetSymbolAddress((void**)&vnacc2,  g_vnacc2);
    cudaGetSymbolAddress((void**)&vnsum2,  g_vnsum2);
    cudaGetSymbolAddress((void**)&cnt,     g_cnt);
    cudaGetSymbolAddress((void**)&rowptrL, g_rowptrL);
    cudaGetSymbolAddress((void**)&esrcL,   g_esrcL);
    cudaGetSymbolAddress((void**)&esrcE,   g_esrcE);
    cudaGetSymbolAddress((void**)&cursor,  g_cursor);
    cudaGetSymbolAddress((void**)&bsum,    g_bsum);

    const size_t nvh = (size_t)NV * HIDDEN;

    // ---- setup (6 launches) ----
    k_setup_all<<<grid1(nvh / 4, 256), 256>>>(
        (const float4*)x, (float4*)xv, exp_edges, esrcE,
        lq_w, lk_w, lv_w, eq_w, ek_w, ev_w,
        lq_b, lk_b, lv_b, eq_b, ek_b, ev_b,
        lo_w, eo_w, lo_b, eo_b, ffn_w1, ffn_w2,
        wqkvh, wqkvl, woh, wol, w1h, w1l, w2h, w2l, bqkv, bo);
    k_zero_i<<<grid1(NV, 256), 256>>>(cnt, NV);
    k_hist<<<grid1(N_EDGES, 256), 256>>>(edge_idx + N_EDGES, N_EDGES, cnt);
    {
        int nblk = (NV + 1023) / 1024;    // 20
        k_scan1<<<nblk, 1024>>>(cnt, rowptrL, bsum, NV);
        k_scan3<<<grid1(NV, 256), 256>>>(rowptrL, bsum, cnt, cursor, NV, nblk);
    }
    k_scatter<<<grid1(N_EDGES, 256), 256>>>(edge_idx, edge_idx + N_EDGES, N_EDGES,
                                            cursor, esrcL);

    // ---- layers ----
    for (int l = 0; l < LAYERS; l++) {
        // qkv = xv @ wqkv + b   (N=768, BM=128 kernel)
        {
            dim3 gg(QKV6 / BN, (NV + BM - 1) / BM);
            k_hgemm<<<gg, 256>>>(xv, wqkvh + (size_t)l * HIDDEN * QKV6,
                                 wqkvl + (size_t)l * HIDDEN * QKV6, bqkv + l * QKV6,
                                 qkv, NV, QKV6, HIDDEN, 0);
        }

        // combined gather (local + expander) + vn partials; 64-thread blocks
        k_gather_both<<<grid1((size_t)(N_NODES + NV) * 32, 64), 64>>>(
            qkv, agg, rowptrL, esrcL, esrcE + (size_t)l * E_EXP);
        k_vn_partial<<<VN_SLOTS * 32 / 64, 64>>>(qkv, vnacc2, vnsum2);

        // fused o-projection + residual + LN (vn-final folded into VN_BLOCK)
        {
            dim3 gg(1, (NV + BM64 - 1) / BM64);
            k_hgemm64_ln<<<gg, 256>>>(agg, agg, vnacc2, vnsum2,
                                      woh + (size_t)l * 256 * HIDDEN,
                                      wol + (size_t)l * 256 * HIDDEN, bo + l * HIDDEN,
                                      xv, ln_g + (size_t)l * HIDDEN,
                                      ln_b + (size_t)l * HIDDEN, NV, 256);
        }

        // FFN1: h1 = gelu(xv@w1+b1)   (N=512, BM=128 kernel)
        {
            dim3 gg(512 / BN, (NV + BM - 1) / BM);
            k_hgemm<<<gg, 256>>>(xv, w1h + (size_t)l * HIDDEN * 512,
                                 w1l + (size_t)l * HIDDEN * 512, ffn_b1 + (size_t)l * 512,
                                 h1, NV, 512, HIDDEN, 2);
        }
        // FFN2: xv += h1@w2+b2 (BM=64; last layer also writes d_out)
        {
            dim3 gg(1, (NV + BM64 - 1) / BM64);
            k_hgemm64_acc<<<gg, 256>>>(h1, w2h + (size_t)l * 512 * HIDDEN,
                                       w2l + (size_t)l * 512 * HIDDEN,
                                       ffn_b2 + (size_t)l * HIDDEN, xv,
                                       (l == LAYERS - 1) ? (float*)d_out : nullptr,
                                       NV, 512);
        }
    }
}